// round 1
// baseline (speedup 1.0000x reference)
#include <cuda_runtime.h>
#include <math.h>

#define BB 32
#define DD 512
#define TT 64
#define RR 49
#define TR 3136
#define KK 64
#define OUTN 1024
#define KD 32768

// ---------------- scratch (static device globals; no dynamic alloc) ----------------
__device__ float g_assign[BB * KK * TR];   // 25.7 MB
__device__ float g_asum[BB * KK];
__device__ float g_vlad[BB * KD];          // 4 MB
__device__ float g_bsq[BB];
__device__ float g_outpre[BB * OUTN];

// ---------------- zero accumulators (replayed every graph launch) ----------------
__global__ void k_zero() {
    int i = blockIdx.x * 256 + threadIdx.x;
    if (i < BB * OUTN) g_outpre[i] = 0.f;
    if (i < BB * KK)   g_asum[i]   = 0.f;
    if (i < BB)        g_bsq[i]    = 0.f;
}

// ---------------- K1: logits + softmax + mask + assign + a_sum ----------------
// grid (B, 14), block 224 threads, each thread owns one tr column.
// dyn smem: conv_w transposed [512][64] (128 KB) + 64-float a_sum buffer.
extern __shared__ float s_k1[];
__global__ __launch_bounds__(224) void k_assign(
    const float* __restrict__ x, const int* __restrict__ mask,
    const float* __restrict__ conv_w)
{
    float* sWT = s_k1;            // [d][k] : d*64 + k
    float* sAs = s_k1 + DD * KK;  // [64]
    const int tid = threadIdx.x;
    const int b = blockIdx.x, chunk = blockIdx.y;

    // stage conv_w transposed: lanes map to consecutive k -> conflict-free STS
    for (int i = tid; i < KK * DD; i += 224) {
        int k = i & 63, d = i >> 6;
        sWT[d * 64 + k] = conv_w[k * DD + d];
    }
    if (tid < 64) sAs[tid] = 0.f;
    __syncthreads();

    const int tr = chunk * 224 + tid;           // 14*224 == 3136, no tail
    const float* xp = x + (size_t)b * DD * TR + tr;

    float acc[64];
#pragma unroll
    for (int k = 0; k < 64; k++) acc[k] = 0.f;

#pragma unroll 4
    for (int d = 0; d < DD; d++) {
        float xv = __ldg(xp + d * TR);          // coalesced across the warp
        const float4* w = (const float4*)(sWT + d * 64);  // broadcast
#pragma unroll
        for (int q = 0; q < 16; q++) {
            float4 wv = w[q];
            acc[4 * q + 0] += wv.x * xv;
            acc[4 * q + 1] += wv.y * xv;
            acc[4 * q + 2] += wv.z * xv;
            acc[4 * q + 3] += wv.w * xv;
        }
    }

    // in-thread softmax over k
    float m = acc[0];
#pragma unroll
    for (int k = 1; k < 64; k++) m = fmaxf(m, acc[k]);
    float s = 0.f;
#pragma unroll
    for (int k = 0; k < 64; k++) { float e = __expf(acc[k] - m); acc[k] = e; s += e; }
    float mv = (float)mask[b * TT + tr / RR];
    float inv = mv / s;

    float* ap = g_assign + (size_t)b * KK * TR + tr;
#pragma unroll
    for (int k = 0; k < 64; k++) {
        float a = acc[k] * inv;
        ap[k * TR] = a;                          // coalesced per k-row
        acc[k] = a;
    }

    // a_sum: warp shuffle-reduce per k, then one smem atomic per warp
    const int lane = tid & 31;
#pragma unroll
    for (int k = 0; k < 64; k++) {
        float v = acc[k];
        v += __shfl_xor_sync(0xffffffffu, v, 16);
        v += __shfl_xor_sync(0xffffffffu, v, 8);
        v += __shfl_xor_sync(0xffffffffu, v, 4);
        v += __shfl_xor_sync(0xffffffffu, v, 2);
        v += __shfl_xor_sync(0xffffffffu, v, 1);
        if (lane == 0) atomicAdd(&sAs[k], v);
    }
    __syncthreads();
    if (tid < 64) atomicAdd(&g_asum[b * 64 + tid], sAs[tid]);
}

// ---------------- K2: vlad[b,k,d] = sum_tr a*x - a_sum*c ----------------
// grid (B, 8 d-tiles of 64), block 256, 4k x 4d micro-tile per thread.
__global__ __launch_bounds__(256) void k_vlad(
    const float* __restrict__ x, const float* __restrict__ centroids)
{
    __shared__ float sA[32 * 68];   // [tr][k], stride 68 (16B aligned, low conflict)
    __shared__ float sX[32 * 68];   // [tr][d]
    const int tid = threadIdx.x;
    const int b = blockIdx.x, d0 = blockIdx.y * 64;
    const int kk = (tid >> 4) * 4;  // 0..60
    const int dd = (tid & 15) * 4;  // 0..60

    float acc[16];
#pragma unroll
    for (int i = 0; i < 16; i++) acc[i] = 0.f;

    const float* ab = g_assign + (size_t)b * KK * TR;
    const float* xb = x + (size_t)b * DD * TR;

    for (int tr0 = 0; tr0 < TR; tr0 += 32) {     // 98 chunks exactly
        __syncthreads();
        for (int i = tid; i < 2048; i += 256) {
            int row = i >> 5, tr = i & 31;
            sA[tr * 68 + row] = ab[row * TR + tr0 + tr];
            sX[tr * 68 + row] = xb[(size_t)(d0 + row) * TR + tr0 + tr];
        }
        __syncthreads();
#pragma unroll
        for (int tr = 0; tr < 32; tr++) {
            float4 a  = *(const float4*)(sA + tr * 68 + kk);
            float4 xv = *(const float4*)(sX + tr * 68 + dd);
            acc[0]  += a.x * xv.x; acc[1]  += a.x * xv.y; acc[2]  += a.x * xv.z; acc[3]  += a.x * xv.w;
            acc[4]  += a.y * xv.x; acc[5]  += a.y * xv.y; acc[6]  += a.y * xv.z; acc[7]  += a.y * xv.w;
            acc[8]  += a.z * xv.x; acc[9]  += a.z * xv.y; acc[10] += a.z * xv.z; acc[11] += a.z * xv.w;
            acc[12] += a.w * xv.x; acc[13] += a.w * xv.y; acc[14] += a.w * xv.z; acc[15] += a.w * xv.w;
        }
    }

#pragma unroll
    for (int i = 0; i < 4; i++) {
        int k = kk + i;
        float as = g_asum[b * 64 + k];
#pragma unroll
        for (int j = 0; j < 4; j++) {
            int d = d0 + dd + j;
            g_vlad[((size_t)b * 64 + k) * 512 + d] =
                acc[i * 4 + j] - as * centroids[k * 512 + d];
        }
    }
}

// ---------------- K3: intra-normalization per (b,k) row + per-b sumsq ----------------
__global__ __launch_bounds__(128) void k_intranorm() {
    __shared__ float sred[4];
    const int row = blockIdx.x;            // b*64 + k
    const int tid = threadIdx.x, lane = tid & 31, w = tid >> 5;
    float4* v = (float4*)(g_vlad + (size_t)row * 512);
    float4 val = v[tid];
    float ss = val.x * val.x + val.y * val.y + val.z * val.z + val.w * val.w;
    ss += __shfl_xor_sync(0xffffffffu, ss, 16);
    ss += __shfl_xor_sync(0xffffffffu, ss, 8);
    ss += __shfl_xor_sync(0xffffffffu, ss, 4);
    ss += __shfl_xor_sync(0xffffffffu, ss, 2);
    ss += __shfl_xor_sync(0xffffffffu, ss, 1);
    if (lane == 0) sred[w] = ss;
    __syncthreads();
    float tot = sred[0] + sred[1] + sred[2] + sred[3];
    float scale = 1.f / fmaxf(sqrtf(tot), 1e-12f);
    val.x *= scale; val.y *= scale; val.z *= scale; val.w *= scale;
    v[tid] = val;
    if (tid == 0) atomicAdd(&g_bsq[row >> 6], tot * scale * scale);
}

// ---------------- K4: out_pre[b,o] += (vlad_n * bscale) . red_w[o,:] ----------------
// grid (32 o-tiles, 8 j-splits), block 256, 2o x 2b per thread.
__global__ __launch_bounds__(256) void k_reduce(const float* __restrict__ red_w) {
    __shared__ float sW[32 * 65];
    __shared__ float sV[32 * 65];
    __shared__ float sBS[32];
    const int tid = threadIdx.x;
    const int o0 = blockIdx.x * 32;
    const int j0 = blockIdx.y * 4096;
    if (tid < 32) sBS[tid] = 1.f / fmaxf(sqrtf(g_bsq[tid]), 1e-12f);
    const int op = (tid & 15) * 2;
    const int bp = (tid >> 4) * 2;
    float a00 = 0.f, a01 = 0.f, a10 = 0.f, a11 = 0.f;

    for (int jc = j0; jc < j0 + 4096; jc += 64) {
        __syncthreads();
        for (int i = tid; i < 2048; i += 256) {
            int r = i >> 6, jj = i & 63;
            sW[r * 65 + jj] = red_w[(size_t)(o0 + r) * KD + jc + jj];
            sV[r * 65 + jj] = g_vlad[(size_t)r * KD + jc + jj] * sBS[r];
        }
        __syncthreads();
#pragma unroll
        for (int jj = 0; jj < 64; jj++) {
            float w0 = sW[op * 65 + jj], w1 = sW[(op + 1) * 65 + jj];
            float v0 = sV[bp * 65 + jj], v1 = sV[(bp + 1) * 65 + jj];
            a00 += w0 * v0; a01 += w0 * v1; a10 += w1 * v0; a11 += w1 * v1;
        }
    }
    atomicAdd(&g_outpre[(size_t)bp * OUTN + o0 + op],           a00);
    atomicAdd(&g_outpre[(size_t)(bp + 1) * OUTN + o0 + op],     a01);
    atomicAdd(&g_outpre[(size_t)bp * OUTN + o0 + op + 1],       a10);
    atomicAdd(&g_outpre[(size_t)(bp + 1) * OUTN + o0 + op + 1], a11);
}

// ---------------- K5: LayerNorm per b ----------------
__global__ __launch_bounds__(256) void k_ln(
    const float* __restrict__ gamma, const float* __restrict__ beta,
    float* __restrict__ out)
{
    __shared__ float sred[8];
    const int b = blockIdx.x, tid = threadIdx.x, lane = tid & 31, w = tid >> 5;
    float4 v = ((const float4*)(g_outpre + (size_t)b * OUTN))[tid];
    float s = v.x + v.y + v.z + v.w;
    s += __shfl_xor_sync(0xffffffffu, s, 16);
    s += __shfl_xor_sync(0xffffffffu, s, 8);
    s += __shfl_xor_sync(0xffffffffu, s, 4);
    s += __shfl_xor_sync(0xffffffffu, s, 2);
    s += __shfl_xor_sync(0xffffffffu, s, 1);
    if (lane == 0) sred[w] = s;
    __syncthreads();
    float tot = 0.f;
#pragma unroll
    for (int i = 0; i < 8; i++) tot += sred[i];
    const float mu = tot * (1.f / 1024.f);

    float dx0 = v.x - mu, dx1 = v.y - mu, dx2 = v.z - mu, dx3 = v.w - mu;
    float vs = dx0 * dx0 + dx1 * dx1 + dx2 * dx2 + dx3 * dx3;
    vs += __shfl_xor_sync(0xffffffffu, vs, 16);
    vs += __shfl_xor_sync(0xffffffffu, vs, 8);
    vs += __shfl_xor_sync(0xffffffffu, vs, 4);
    vs += __shfl_xor_sync(0xffffffffu, vs, 2);
    vs += __shfl_xor_sync(0xffffffffu, vs, 1);
    __syncthreads();
    if (lane == 0) sred[w] = vs;
    __syncthreads();
    float vtot = 0.f;
#pragma unroll
    for (int i = 0; i < 8; i++) vtot += sred[i];
    const float inv = 1.f / sqrtf(vtot * (1.f / 1024.f) + 1e-5f);

    float4 gm = ((const float4*)gamma)[tid];
    float4 be = ((const float4*)beta)[tid];
    float4 r;
    r.x = dx0 * inv * gm.x + be.x;
    r.y = dx1 * inv * gm.y + be.y;
    r.z = dx2 * inv * gm.z + be.z;
    r.w = dx3 * inv * gm.w + be.w;
    ((float4*)(out + (size_t)b * OUTN))[tid] = r;
}

// ---------------- launch ----------------
extern "C" void kernel_launch(void* const* d_in, const int* in_sizes, int n_in,
                              void* d_out, int out_size)
{
    const float* x         = (const float*)d_in[0];
    const int*   mask      = (const int*)d_in[1];
    const float* centroids = (const float*)d_in[2];
    const float* conv_w    = (const float*)d_in[3];
    const float* red_w     = (const float*)d_in[4];
    const float* gamma     = (const float*)d_in[5];
    const float* beta      = (const float*)d_in[6];
    float* out = (float*)d_out;

    const int smem_k1 = (DD * KK + 64) * (int)sizeof(float);  // 131328 B
    cudaFuncSetAttribute(k_assign, cudaFuncAttributeMaxDynamicSharedMemorySize, smem_k1);

    k_zero<<<128, 256>>>();
    k_assign<<<dim3(BB, 14), 224, smem_k1>>>(x, mask, conv_w);
    k_vlad<<<dim3(BB, 8), 256>>>(x, centroids);
    k_intranorm<<<BB * KK, 128>>>();
    k_reduce<<<dim3(32, 8), 256>>>(red_w);
    k_ln<<<BB, 256>>>(gamma, beta, out);
}

// round 2
// speedup vs baseline: 1.2577x; 1.2577x over previous
#include <cuda_runtime.h>
#include <math.h>

#define BB 32
#define DD 512
#define TT 64
#define RR 49
#define TR 3136
#define KK 64
#define OUTN 1024
#define KD 32768

typedef unsigned long long ull;

// ---------------- f32x2 packed-math helpers (FFMA2 is PTX-only) ----------------
__device__ __forceinline__ ull pack2(float lo, float hi) {
    ull r; asm("mov.b64 %0, {%1,%2};" : "=l"(r) : "f"(lo), "f"(hi)); return r;
}
__device__ __forceinline__ void fma2(ull& d, ull a, ull b) {
    asm("fma.rn.f32x2 %0, %1, %2, %0;" : "+l"(d) : "l"(a), "l"(b));
}
__device__ __forceinline__ float2 unpack2(ull v) {
    float2 f; asm("mov.b64 {%0,%1}, %2;" : "=f"(f.x), "=f"(f.y) : "l"(v)); return f;
}

// ---------------- scratch ----------------
__device__ float g_assign[BB * KK * TR];   // 25.7 MB
__device__ float g_asum[BB * KK];
__device__ float g_vlad[BB * KD];          // 4 MB
__device__ float g_bsq[BB];
__device__ float g_outpre[BB * OUTN];

__global__ void k_zero() {
    int i = blockIdx.x * 256 + threadIdx.x;
    if (i < BB * OUTN) g_outpre[i] = 0.f;
    if (i < BB * KK)   g_asum[i]   = 0.f;
    if (i < BB)        g_bsq[i]    = 0.f;
}

// ---------------- K1: logits + softmax + mask + assign + a_sum ----------------
// grid (B, 14), block 224. Weights restaged as d-pair-interleaved rows so the
// inner product packs along the reduction dim: 64 FFMA2 + 32 LDS.128 per d-pair.
extern __shared__ float s_k1[];
__global__ __launch_bounds__(224) void k_assign(
    const float* __restrict__ x, const int* __restrict__ mask,
    const float* __restrict__ conv_w)
{
    float* sW2 = s_k1;                 // [256 d-pairs][132] : row p holds (w[2p,k],w[2p+1,k]) pairs
    float* sAs = s_k1 + 256 * 132;     // [64]
    const int tid = threadIdx.x;
    const int b = blockIdx.x, chunk = blockIdx.y;

    // stage: coalesced read of conv_w, interleaved write (pad 132 -> ~2-way STS)
    for (int i = tid; i < KK * DD; i += 224) {
        int k = i >> 9, d = i & 511;
        sW2[(d >> 1) * 132 + 2 * k + (d & 1)] = conv_w[k * DD + d];
    }
    if (tid < 64) sAs[tid] = 0.f;
    __syncthreads();

    const int tr = chunk * 224 + tid;            // 14*224 == 3136
    const float* xp = x + (size_t)b * DD * TR + tr;

    ull acc[64];
#pragma unroll
    for (int k = 0; k < 64; k++) acc[k] = 0ULL;

    // 2-deep LDG prefetch of the x pair
    float xa0 = __ldg(xp);
    float xa1 = __ldg(xp + TR);
    float xb0 = __ldg(xp + 2 * TR);
    float xb1 = __ldg(xp + 3 * TR);

    for (int p = 0; p < 256; p++) {
        ull xx = pack2(xa0, xa1);
        xa0 = xb0; xa1 = xb1;
        if (p + 2 < 256) {
            xb0 = __ldg(xp + (2 * p + 4) * TR);
            xb1 = __ldg(xp + (2 * p + 5) * TR);
        }
        const ulonglong2* w = (const ulonglong2*)(sW2 + p * 132);  // broadcast
#pragma unroll
        for (int q = 0; q < 32; q++) {
            ulonglong2 wv = w[q];          // pairs for k=2q, 2q+1
            fma2(acc[2 * q],     wv.x, xx);
            fma2(acc[2 * q + 1], wv.y, xx);
        }
    }

    // collapse pairs, then in-thread softmax over k
    float v[64];
#pragma unroll
    for (int k = 0; k < 64; k++) { float2 f = unpack2(acc[k]); v[k] = f.x + f.y; }
    float m = v[0];
#pragma unroll
    for (int k = 1; k < 64; k++) m = fmaxf(m, v[k]);
    float s = 0.f;
#pragma unroll
    for (int k = 0; k < 64; k++) { float e = __expf(v[k] - m); v[k] = e; s += e; }
    float mv = (float)mask[b * TT + tr / RR];
    float inv = mv / s;

    float* ap = g_assign + (size_t)b * KK * TR + tr;
#pragma unroll
    for (int k = 0; k < 64; k++) {
        float a = v[k] * inv;
        ap[k * TR] = a;
        v[k] = a;
    }

    const int lane = tid & 31;
#pragma unroll
    for (int k = 0; k < 64; k++) {
        float t = v[k];
        t += __shfl_xor_sync(0xffffffffu, t, 16);
        t += __shfl_xor_sync(0xffffffffu, t, 8);
        t += __shfl_xor_sync(0xffffffffu, t, 4);
        t += __shfl_xor_sync(0xffffffffu, t, 2);
        t += __shfl_xor_sync(0xffffffffu, t, 1);
        if (lane == 0) atomicAdd(&sAs[k], t);
    }
    __syncthreads();
    if (tid < 64) atomicAdd(&g_asum[b * 64 + tid], sAs[tid]);
}

// ---------------- K2: vlad[b,k,d] = sum_tr a*x - a_sum*c ----------------
// grid (B, 4 d-tiles of 128), block 256. Micro-tile 4k x 8d (4 d-pairs),
// packed along d. Register double-buffered staging hides DRAM latency.
__global__ __launch_bounds__(256) void k_vlad(
    const float* __restrict__ x, const float* __restrict__ centroids)
{
    __shared__ float sA[32 * 68];    // [tr][k]
    __shared__ float sX[32 * 132];   // [tr][d], 128 d + pad
    const int tid = threadIdx.x;
    const int b = blockIdx.x, d0 = blockIdx.y * 128;
    const int kk = (tid >> 4) * 4;   // 0..60
    const int dd = (tid & 15) * 8;   // 0..120

    ull acc[16];
#pragma unroll
    for (int i = 0; i < 16; i++) acc[i] = 0ULL;

    const float* ab = g_assign + (size_t)b * KK * TR;
    const float* xb = x + (size_t)b * DD * TR;

    float ra[8], rx[16];
    // prefetch chunk 0
#pragma unroll
    for (int j = 0; j < 8; j++) {
        int idx = tid + j * 256, row = idx >> 5, t = idx & 31;
        ra[j] = ab[row * TR + t];
    }
#pragma unroll
    for (int j = 0; j < 16; j++) {
        int idx = tid + j * 256, row = idx >> 5, t = idx & 31;
        rx[j] = xb[(size_t)(d0 + row) * TR + t];
    }

    for (int c = 0; c < 98; c++) {
        __syncthreads();
#pragma unroll
        for (int j = 0; j < 8; j++) {
            int idx = tid + j * 256, row = idx >> 5, t = idx & 31;
            sA[t * 68 + row] = ra[j];
        }
#pragma unroll
        for (int j = 0; j < 16; j++) {
            int idx = tid + j * 256, row = idx >> 5, t = idx & 31;
            sX[t * 132 + row] = rx[j];
        }
        __syncthreads();

        if (c + 1 < 98) {
            int tr0 = (c + 1) * 32;
#pragma unroll
            for (int j = 0; j < 8; j++) {
                int idx = tid + j * 256, row = idx >> 5, t = idx & 31;
                ra[j] = ab[row * TR + tr0 + t];
            }
#pragma unroll
            for (int j = 0; j < 16; j++) {
                int idx = tid + j * 256, row = idx >> 5, t = idx & 31;
                rx[j] = xb[(size_t)(d0 + row) * TR + tr0 + t];
            }
        }

#pragma unroll
        for (int t = 0; t < 32; t++) {
            float4 a = *(const float4*)(sA + t * 68 + kk);
            ulonglong2 xv0 = *(const ulonglong2*)(sX + t * 132 + dd);
            ulonglong2 xv1 = *(const ulonglong2*)(sX + t * 132 + dd + 4);
            ull a0 = pack2(a.x, a.x), a1 = pack2(a.y, a.y);
            ull a2 = pack2(a.z, a.z), a3 = pack2(a.w, a.w);
            fma2(acc[0],  a0, xv0.x); fma2(acc[1],  a0, xv0.y);
            fma2(acc[2],  a0, xv1.x); fma2(acc[3],  a0, xv1.y);
            fma2(acc[4],  a1, xv0.x); fma2(acc[5],  a1, xv0.y);
            fma2(acc[6],  a1, xv1.x); fma2(acc[7],  a1, xv1.y);
            fma2(acc[8],  a2, xv0.x); fma2(acc[9],  a2, xv0.y);
            fma2(acc[10], a2, xv1.x); fma2(acc[11], a2, xv1.y);
            fma2(acc[12], a3, xv0.x); fma2(acc[13], a3, xv0.y);
            fma2(acc[14], a3, xv1.x); fma2(acc[15], a3, xv1.y);
        }
    }

#pragma unroll
    for (int i = 0; i < 4; i++) {
        int k = kk + i;
        float as = g_asum[b * 64 + k];
#pragma unroll
        for (int j = 0; j < 4; j++) {
            int d = d0 + dd + 2 * j;
            float2 f = unpack2(acc[i * 4 + j]);
            float2 cv = *(const float2*)(centroids + k * 512 + d);
            float2 o;
            o.x = f.x - as * cv.x;
            o.y = f.y - as * cv.y;
            *(float2*)(g_vlad + ((size_t)b * 64 + k) * 512 + d) = o;
        }
    }
}

// ---------------- K3: intra-normalization per (b,k) row + per-b sumsq ----------------
__global__ __launch_bounds__(128) void k_intranorm() {
    __shared__ float sred[4];
    const int row = blockIdx.x;            // b*64 + k
    const int tid = threadIdx.x, lane = tid & 31, w = tid >> 5;
    float4* v = (float4*)(g_vlad + (size_t)row * 512);
    float4 val = v[tid];
    float ss = val.x * val.x + val.y * val.y + val.z * val.z + val.w * val.w;
    ss += __shfl_xor_sync(0xffffffffu, ss, 16);
    ss += __shfl_xor_sync(0xffffffffu, ss, 8);
    ss += __shfl_xor_sync(0xffffffffu, ss, 4);
    ss += __shfl_xor_sync(0xffffffffu, ss, 2);
    ss += __shfl_xor_sync(0xffffffffu, ss, 1);
    if (lane == 0) sred[w] = ss;
    __syncthreads();
    float tot = sred[0] + sred[1] + sred[2] + sred[3];
    float scale = 1.f / fmaxf(sqrtf(tot), 1e-12f);
    val.x *= scale; val.y *= scale; val.z *= scale; val.w *= scale;
    v[tid] = val;
    if (tid == 0) atomicAdd(&g_bsq[row >> 6], tot * scale * scale);
}

// ---------------- K4: out_pre[b,o] += (vlad_n * bscale) . red_w[o,:] ----------------
// grid (32 o-tiles, 8 j-splits), block 256. Packed along jj (reduction):
// 8 FFMA2 + 4 LDS.128 per 4 jj per thread. Register double-buffered staging.
__global__ __launch_bounds__(256) void k_reduce(const float* __restrict__ red_w) {
    __shared__ float sW[32 * 68];
    __shared__ float sV[32 * 68];
    __shared__ float sBS[32];
    const int tid = threadIdx.x;
    const int o0 = blockIdx.x * 32;
    const int j0 = blockIdx.y * 4096;
    if (tid < 32) sBS[tid] = 1.f / fmaxf(sqrtf(g_bsq[tid]), 1e-12f);
    const int op = (tid & 15) * 2;
    const int bp = (tid >> 4) * 2;
    ull a00 = 0ULL, a01 = 0ULL, a10 = 0ULL, a11 = 0ULL;

    float rw[8], rv[8];
#pragma unroll
    for (int j = 0; j < 8; j++) {
        int idx = tid + j * 256, r = idx >> 6, jj = idx & 63;
        rw[j] = red_w[(size_t)(o0 + r) * KD + j0 + jj];
        rv[j] = g_vlad[(size_t)r * KD + j0 + jj];
    }

    for (int c = 0; c < 64; c++) {
        __syncthreads();
#pragma unroll
        for (int j = 0; j < 8; j++) {
            int idx = tid + j * 256, r = idx >> 6, jj = idx & 63;
            sW[r * 68 + jj] = rw[j];
            sV[r * 68 + jj] = rv[j] * sBS[r];
        }
        __syncthreads();

        if (c + 1 < 64) {
            int jc = j0 + (c + 1) * 64;
#pragma unroll
            for (int j = 0; j < 8; j++) {
                int idx = tid + j * 256, r = idx >> 6, jj = idx & 63;
                rw[j] = red_w[(size_t)(o0 + r) * KD + jc + jj];
                rv[j] = g_vlad[(size_t)r * KD + jc + jj];
            }
        }

        const ulonglong2* wp0 = (const ulonglong2*)(sW + op * 68);
        const ulonglong2* wp1 = (const ulonglong2*)(sW + (op + 1) * 68);
        const ulonglong2* vp0 = (const ulonglong2*)(sV + bp * 68);
        const ulonglong2* vp1 = (const ulonglong2*)(sV + (bp + 1) * 68);
#pragma unroll
        for (int q = 0; q < 16; q++) {
            ulonglong2 w0 = wp0[q], w1 = wp1[q];
            ulonglong2 v0 = vp0[q], v1 = vp1[q];
            fma2(a00, w0.x, v0.x); fma2(a00, w0.y, v0.y);
            fma2(a01, w0.x, v1.x); fma2(a01, w0.y, v1.y);
            fma2(a10, w1.x, v0.x); fma2(a10, w1.y, v0.y);
            fma2(a11, w1.x, v1.x); fma2(a11, w1.y, v1.y);
        }
    }
    float2 f00 = unpack2(a00), f01 = unpack2(a01), f10 = unpack2(a10), f11 = unpack2(a11);
    atomicAdd(&g_outpre[(size_t)bp * OUTN + o0 + op],           f00.x + f00.y);
    atomicAdd(&g_outpre[(size_t)(bp + 1) * OUTN + o0 + op],     f01.x + f01.y);
    atomicAdd(&g_outpre[(size_t)bp * OUTN + o0 + op + 1],       f10.x + f10.y);
    atomicAdd(&g_outpre[(size_t)(bp + 1) * OUTN + o0 + op + 1], f11.x + f11.y);
}

// ---------------- K5: LayerNorm per b ----------------
__global__ __launch_bounds__(256) void k_ln(
    const float* __restrict__ gamma, const float* __restrict__ beta,
    float* __restrict__ out)
{
    __shared__ float sred[8];
    const int b = blockIdx.x, tid = threadIdx.x, lane = tid & 31, w = tid >> 5;
    float4 v = ((const float4*)(g_outpre + (size_t)b * OUTN))[tid];
    float s = v.x + v.y + v.z + v.w;
    s += __shfl_xor_sync(0xffffffffu, s, 16);
    s += __shfl_xor_sync(0xffffffffu, s, 8);
    s += __shfl_xor_sync(0xffffffffu, s, 4);
    s += __shfl_xor_sync(0xffffffffu, s, 2);
    s += __shfl_xor_sync(0xffffffffu, s, 1);
    if (lane == 0) sred[w] = s;
    __syncthreads();
    float tot = 0.f;
#pragma unroll
    for (int i = 0; i < 8; i++) tot += sred[i];
    const float mu = tot * (1.f / 1024.f);

    float dx0 = v.x - mu, dx1 = v.y - mu, dx2 = v.z - mu, dx3 = v.w - mu;
    float vs = dx0 * dx0 + dx1 * dx1 + dx2 * dx2 + dx3 * dx3;
    vs += __shfl_xor_sync(0xffffffffu, vs, 16);
    vs += __shfl_xor_sync(0xffffffffu, vs, 8);
    vs += __shfl_xor_sync(0xffffffffu, vs, 4);
    vs += __shfl_xor_sync(0xffffffffu, vs, 2);
    vs += __shfl_xor_sync(0xffffffffu, vs, 1);
    __syncthreads();
    if (lane == 0) sred[w] = vs;
    __syncthreads();
    float vtot = 0.f;
#pragma unroll
    for (int i = 0; i < 8; i++) vtot += sred[i];
    const float inv = 1.f / sqrtf(vtot * (1.f / 1024.f) + 1e-5f);

    float4 gm = ((const float4*)gamma)[tid];
    float4 be = ((const float4*)beta)[tid];
    float4 r;
    r.x = dx0 * inv * gm.x + be.x;
    r.y = dx1 * inv * gm.y + be.y;
    r.z = dx2 * inv * gm.z + be.z;
    r.w = dx3 * inv * gm.w + be.w;
    ((float4*)(out + (size_t)b * OUTN))[tid] = r;
}

// ---------------- launch ----------------
extern "C" void kernel_launch(void* const* d_in, const int* in_sizes, int n_in,
                              void* d_out, int out_size)
{
    const float* x         = (const float*)d_in[0];
    const int*   mask      = (const int*)d_in[1];
    const float* centroids = (const float*)d_in[2];
    const float* conv_w    = (const float*)d_in[3];
    const float* red_w     = (const float*)d_in[4];
    const float* gamma     = (const float*)d_in[5];
    const float* beta      = (const float*)d_in[6];
    float* out = (float*)d_out;

    const int smem_k1 = (256 * 132 + 64) * (int)sizeof(float);  // 135424 B
    cudaFuncSetAttribute(k_assign, cudaFuncAttributeMaxDynamicSharedMemorySize, smem_k1);

    k_zero<<<128, 256>>>();
    k_assign<<<dim3(BB, 14), 224, smem_k1>>>(x, mask, conv_w);
    k_vlad<<<dim3(BB, 4), 256>>>(x, centroids);
    k_intranorm<<<BB * KK, 128>>>();
    k_reduce<<<dim3(32, 8), 256>>>(red_w);
    k_ln<<<BB, 256>>>(gamma, beta, out);
}

// round 5
// speedup vs baseline: 2.0078x; 1.5964x over previous
#include <cuda_runtime.h>
#include <cuda_bf16.h>
#include <math.h>
#include <cstdint>

#define BB 32
#define DD 512
#define TT 64
#define RR 49
#define TR 3136
#define TRP 3200        // 25*128
#define KK 64
#define OUTN 1024
#define KD 32768

typedef unsigned long long ull;

// ================= mma.sync m16n8k16 bf16 (sm_80+ base target) =================
__device__ __forceinline__ void mma_bf16(float* c, const uint32_t* a, const uint32_t* b) {
    asm volatile(
        "mma.sync.aligned.m16n8k16.row.col.f32.bf16.bf16.f32 "
        "{%0,%1,%2,%3}, {%4,%5,%6,%7}, {%8,%9}, {%0,%1,%2,%3};"
        : "+f"(c[0]), "+f"(c[1]), "+f"(c[2]), "+f"(c[3])
        : "r"(a[0]), "r"(a[1]), "r"(a[2]), "r"(a[3]), "r"(b[0]), "r"(b[1]));
}

__device__ __forceinline__ void split_bf(float f, __nv_bfloat16& h, __nv_bfloat16& l) {
    h = __float2bfloat16(f);
    l = __float2bfloat16(f - __bfloat162float(h));
}
__device__ __forceinline__ uint32_t pkbf(__nv_bfloat16 a, __nv_bfloat16 b) {
    return (uint32_t)__bfloat16_as_ushort(a) | ((uint32_t)__bfloat16_as_ushort(b) << 16);
}

// ================= f32x2 helpers (k_reduce) =================
__device__ __forceinline__ void fma2(ull& d, ull a, ull b) {
    asm("fma.rn.f32x2 %0, %1, %2, %0;" : "+l"(d) : "l"(a), "l"(b));
}
__device__ __forceinline__ float2 unpack2(ull v) {
    float2 f; asm("mov.b64 {%0,%1}, %2;" : "=f"(f.x), "=f"(f.y) : "l"(v)); return f;
}

// ================= scratch =================
__device__ __align__(256) __nv_bfloat16 g_xT_hi[(size_t)BB * TRP * DD];   // 105 MB
__device__ __align__(256) __nv_bfloat16 g_xT_lo[(size_t)BB * TRP * DD];
__device__ __align__(256) __nv_bfloat16 g_w_hi[KK * DD];
__device__ __align__(256) __nv_bfloat16 g_w_lo[KK * DD];
__device__ __align__(256) __nv_bfloat16 g_ass_hi[(size_t)BB * KK * TR];   // 12.8 MB
__device__ __align__(256) __nv_bfloat16 g_ass_lo[(size_t)BB * KK * TR];
__device__ __align__(256) float g_asum[BB * KK];
__device__ __align__(256) float g_vlad[BB * KD];
__device__ __align__(256) float g_bsq[BB];
__device__ __align__(256) float g_outpre[BB * OUTN];

__global__ void k_zero() {
    int i = blockIdx.x * 256 + threadIdx.x;
    if (i < BB * OUTN) g_outpre[i] = 0.f;
    if (i < BB * KK)   g_asum[i]   = 0.f;
    if (i < BB)        g_bsq[i]    = 0.f;
}

__global__ __launch_bounds__(512) void k_wsplit(const float* __restrict__ conv_w) {
    int i = blockIdx.x * 512 + threadIdx.x;
    if (i < KK * DD) {
        __nv_bfloat16 h, l; split_bf(conv_w[i], h, l);
        g_w_hi[i] = h; g_w_lo[i] = l;
    }
}

// ================= transpose + split: x[b,d,tr] -> xT[b,tr,d] hi/lo =================
__global__ __launch_bounds__(256) void k_transpose(const float* __restrict__ x) {
    __shared__ float t[32][33];
    const int b = blockIdx.x, tr0 = blockIdx.y * 32, d0 = blockIdx.z * 32;
    const int tx = threadIdx.x, ty = threadIdx.y;
#pragma unroll
    for (int i = 0; i < 4; i++)
        t[ty + 8 * i][tx] = x[((size_t)b * DD + d0 + ty + 8 * i) * TR + tr0 + tx];
    __syncthreads();
#pragma unroll
    for (int i = 0; i < 4; i++) {
        int tr = tr0 + ty + 8 * i;
        float f = t[tx][ty + 8 * i];
        __nv_bfloat16 h, l; split_bf(f, h, l);
        size_t o = ((size_t)b * TRP + tr) * DD + d0 + tx;
        g_xT_hi[o] = h; g_xT_lo[o] = l;
    }
}

// ================= GEMM1: logits -> softmax -> assign + a_sum =================
// grid (32, 25), block 256 (8 warps). C tile [128 tr x 64 k], warp = 16-tr strip.
// smem rows padded to 72 bf16 (word stride 36 == 4 mod 32 -> conflict-free frags).
#define SROW 72
#define G1_SMEM ((128 * SROW + 128 * SROW + 64 * SROW + 64 * SROW) * 2 + 256)

extern __shared__ unsigned char smx[];

__global__ __launch_bounds__(256) void k_g1(const int* __restrict__ mask) {
    uint16_t* XH = (uint16_t*)smx;               // [128][72]
    uint16_t* XL = XH + 128 * SROW;
    uint16_t* WH = XL + 128 * SROW;              // [64][72]
    uint16_t* WL = WH + 64 * SROW;
    float*   sAs = (float*)(WL + 64 * SROW);     // [64]

    const int tid = threadIdx.x, wid = tid >> 5, lane = tid & 31;
    const int g = lane >> 2, t = lane & 3;
    const int b = blockIdx.x, tr0 = blockIdx.y * 128;

    if (tid < 64) sAs[tid] = 0.f;

    float cacc[8][4];
#pragma unroll
    for (int n = 0; n < 8; n++)
#pragma unroll
        for (int i = 0; i < 4; i++) cacc[n][i] = 0.f;

    for (int q = 0; q < 8; q++) {               // d chunks of 64
        __syncthreads();
        for (int u = tid; u < 1024; u += 256) {  // X chunk [128 tr][64 d]
            int row = u >> 3, c8 = u & 7;
            size_t src = ((size_t)b * TRP + tr0 + row) * DD + q * 64 + c8 * 8;
            *(uint4*)(XH + row * SROW + c8 * 8) = *(const uint4*)(g_xT_hi + src);
            *(uint4*)(XL + row * SROW + c8 * 8) = *(const uint4*)(g_xT_lo + src);
        }
        for (int u = tid; u < 512; u += 256) {   // W chunk [64 k][64 d]
            int row = u >> 3, c8 = u & 7;
            size_t src = (size_t)row * DD + q * 64 + c8 * 8;
            *(uint4*)(WH + row * SROW + c8 * 8) = *(const uint4*)(g_w_hi + src);
            *(uint4*)(WL + row * SROW + c8 * 8) = *(const uint4*)(g_w_lo + src);
        }
        __syncthreads();

#pragma unroll
        for (int s = 0; s < 4; s++) {
            const int col = s * 16 + 2 * t;
            const int ra = wid * 16 + g;
            uint32_t ah[4], al[4];
            ah[0] = *(const uint32_t*)(XH + ra * SROW + col);
            ah[1] = *(const uint32_t*)(XH + (ra + 8) * SROW + col);
            ah[2] = *(const uint32_t*)(XH + ra * SROW + col + 8);
            ah[3] = *(const uint32_t*)(XH + (ra + 8) * SROW + col + 8);
            al[0] = *(const uint32_t*)(XL + ra * SROW + col);
            al[1] = *(const uint32_t*)(XL + (ra + 8) * SROW + col);
            al[2] = *(const uint32_t*)(XL + ra * SROW + col + 8);
            al[3] = *(const uint32_t*)(XL + (ra + 8) * SROW + col + 8);
#pragma unroll
            for (int n = 0; n < 8; n++) {
                const int rb = n * 8 + g;
                uint32_t bh[2], bl[2];
                bh[0] = *(const uint32_t*)(WH + rb * SROW + col);
                bh[1] = *(const uint32_t*)(WH + rb * SROW + col + 8);
                bl[0] = *(const uint32_t*)(WL + rb * SROW + col);
                bl[1] = *(const uint32_t*)(WL + rb * SROW + col + 8);
                mma_bf16(cacc[n], ah, bh);
                mma_bf16(cacc[n], ah, bl);
                mma_bf16(cacc[n], al, bh);
            }
        }
    }

    // epilogue: rows tra = tr0+wid*16+g, trb = tra+8; cols k = n*8+2t+{0,1}
    const int tra = tr0 + wid * 16 + g;
    const int trb = tra + 8;
    float ma = -1e30f, mb = -1e30f;
#pragma unroll
    for (int n = 0; n < 8; n++) {
        ma = fmaxf(ma, fmaxf(cacc[n][0], cacc[n][1]));
        mb = fmaxf(mb, fmaxf(cacc[n][2], cacc[n][3]));
    }
    ma = fmaxf(ma, __shfl_xor_sync(0xffffffffu, ma, 1));
    ma = fmaxf(ma, __shfl_xor_sync(0xffffffffu, ma, 2));
    mb = fmaxf(mb, __shfl_xor_sync(0xffffffffu, mb, 1));
    mb = fmaxf(mb, __shfl_xor_sync(0xffffffffu, mb, 2));
    float sa = 0.f, sb = 0.f;
#pragma unroll
    for (int n = 0; n < 8; n++) {
        cacc[n][0] = __expf(cacc[n][0] - ma); sa += cacc[n][0];
        cacc[n][1] = __expf(cacc[n][1] - ma); sa += cacc[n][1];
        cacc[n][2] = __expf(cacc[n][2] - mb); sb += cacc[n][2];
        cacc[n][3] = __expf(cacc[n][3] - mb); sb += cacc[n][3];
    }
    sa += __shfl_xor_sync(0xffffffffu, sa, 1);
    sa += __shfl_xor_sync(0xffffffffu, sa, 2);
    sb += __shfl_xor_sync(0xffffffffu, sb, 1);
    sb += __shfl_xor_sync(0xffffffffu, sb, 2);
    const float mva = (tra < TR) ? (float)mask[b * TT + tra / RR] : 0.f;
    const float mvb = (trb < TR) ? (float)mask[b * TT + trb / RR] : 0.f;
    const float inva = mva / sa, invb = mvb / sb;

#pragma unroll
    for (int n = 0; n < 8; n++) {
#pragma unroll
        for (int i = 0; i < 2; i++) {
            const int k = n * 8 + 2 * t + i;
            float aa = cacc[n][i] * inva;
            float ab = cacc[n][2 + i] * invb;
            if (tra < TR) {
                __nv_bfloat16 h, l; split_bf(aa, h, l);
                size_t o = ((size_t)b * KK + k) * TR + tra;
                g_ass_hi[o] = h; g_ass_lo[o] = l;
            }
            if (trb < TR) {
                __nv_bfloat16 h, l; split_bf(ab, h, l);
                size_t o = ((size_t)b * KK + k) * TR + trb;
                g_ass_hi[o] = h; g_ass_lo[o] = l;
            }
            float sum = aa + ab;
            sum += __shfl_xor_sync(0xffffffffu, sum, 4);
            sum += __shfl_xor_sync(0xffffffffu, sum, 8);
            sum += __shfl_xor_sync(0xffffffffu, sum, 16);
            if (g == 0) atomicAdd(&sAs[k], sum);
        }
    }
    __syncthreads();
    if (tid < 64) atomicAdd(&g_asum[b * 64 + tid], sAs[tid]);
}

// ================= GEMM2: vlad[b,k,d] = sum_tr a*x - a_sum*c =================
// grid (32, 4), block 256. C tile [128 d x 64 k], warp = 16-d strip. reduction tr.
#define G2_SMEM ((128 * SROW + 128 * SROW + 64 * SROW + 64 * SROW) * 2 + 256)

__global__ __launch_bounds__(256) void k_g2(const float* __restrict__ x,
                                            const float* __restrict__ centroids) {
    uint16_t* XH = (uint16_t*)smx;               // [128 d][72 tr]
    uint16_t* XL = XH + 128 * SROW;
    uint16_t* AH = XL + 128 * SROW;              // [64 k][72 tr]
    uint16_t* AL = AH + 64 * SROW;
    float*   sAS = (float*)(AL + 64 * SROW);     // [64] a_sum

    const int tid = threadIdx.x, wid = tid >> 5, lane = tid & 31;
    const int g = lane >> 2, t = lane & 3;
    const int b = blockIdx.x, d0 = blockIdx.y * 128;

    if (tid < 64) sAS[tid] = g_asum[b * 64 + tid];

    float cacc[8][4];
#pragma unroll
    for (int n = 0; n < 8; n++)
#pragma unroll
        for (int i = 0; i < 4; i++) cacc[n][i] = 0.f;

    for (int c = 0; c < 49; c++) {               // tr chunks of 64
        const int trc = c * 64;
        __syncthreads();
        for (int u = tid; u < 2048; u += 256) {  // x chunk [128 d][64 tr], fp32->hi/lo
            int row = u >> 4, c4 = u & 15;
            float4 xv = *(const float4*)(x + ((size_t)b * DD + d0 + row) * TR + trc + c4 * 4);
            __nv_bfloat16 h0, l0, h1, l1, h2, l2, h3, l3;
            split_bf(xv.x, h0, l0); split_bf(xv.y, h1, l1);
            split_bf(xv.z, h2, l2); split_bf(xv.w, h3, l3);
            uint2 vh = { pkbf(h0, h1), pkbf(h2, h3) };
            uint2 vl = { pkbf(l0, l1), pkbf(l2, l3) };
            *(uint2*)(XH + row * SROW + c4 * 4) = vh;
            *(uint2*)(XL + row * SROW + c4 * 4) = vl;
        }
        for (int u = tid; u < 512; u += 256) {   // assign chunk [64 k][64 tr]
            int row = u >> 3, c8 = u & 7;
            size_t src = ((size_t)b * KK + row) * TR + trc + c8 * 8;
            *(uint4*)(AH + row * SROW + c8 * 8) = *(const uint4*)(g_ass_hi + src);
            *(uint4*)(AL + row * SROW + c8 * 8) = *(const uint4*)(g_ass_lo + src);
        }
        __syncthreads();

#pragma unroll
        for (int s = 0; s < 4; s++) {
            const int col = s * 16 + 2 * t;
            const int ra = wid * 16 + g;
            uint32_t ah[4], al[4];
            ah[0] = *(const uint32_t*)(XH + ra * SROW + col);
            ah[1] = *(const uint32_t*)(XH + (ra + 8) * SROW + col);
            ah[2] = *(const uint32_t*)(XH + ra * SROW + col + 8);
            ah[3] = *(const uint32_t*)(XH + (ra + 8) * SROW + col + 8);
            al[0] = *(const uint32_t*)(XL + ra * SROW + col);
            al[1] = *(const uint32_t*)(XL + (ra + 8) * SROW + col);
            al[2] = *(const uint32_t*)(XL + ra * SROW + col + 8);
            al[3] = *(const uint32_t*)(XL + (ra + 8) * SROW + col + 8);
#pragma unroll
            for (int n = 0; n < 8; n++) {
                const int rb = n * 8 + g;
                uint32_t bh[2], bl[2];
                bh[0] = *(const uint32_t*)(AH + rb * SROW + col);
                bh[1] = *(const uint32_t*)(AH + rb * SROW + col + 8);
                bl[0] = *(const uint32_t*)(AL + rb * SROW + col);
                bl[1] = *(const uint32_t*)(AL + rb * SROW + col + 8);
                mma_bf16(cacc[n], ah, bh);
                mma_bf16(cacc[n], ah, bl);
                mma_bf16(cacc[n], al, bh);
            }
        }
    }

    // epilogue: rows d = d0+wid*16+g (+8), cols k = n*8+2t+{0,1}
    const int da = d0 + wid * 16 + g;
    const int db = da + 8;
#pragma unroll
    for (int n = 0; n < 8; n++) {
#pragma unroll
        for (int i = 0; i < 2; i++) {
            const int k = n * 8 + 2 * t + i;
            const float as = sAS[k];
            g_vlad[((size_t)b * KK + k) * DD + da] =
                cacc[n][i] - as * centroids[k * DD + da];
            g_vlad[((size_t)b * KK + k) * DD + db] =
                cacc[n][2 + i] - as * centroids[k * DD + db];
        }
    }
}

// ================= K3: intra-normalization =================
__global__ __launch_bounds__(128) void k_intranorm() {
    __shared__ float sred[4];
    const int row = blockIdx.x;
    const int tid = threadIdx.x, lane = tid & 31, w = tid >> 5;
    float4* v = (float4*)(g_vlad + (size_t)row * 512);
    float4 val = v[tid];
    float ss = val.x * val.x + val.y * val.y + val.z * val.z + val.w * val.w;
    ss += __shfl_xor_sync(0xffffffffu, ss, 16);
    ss += __shfl_xor_sync(0xffffffffu, ss, 8);
    ss += __shfl_xor_sync(0xffffffffu, ss, 4);
    ss += __shfl_xor_sync(0xffffffffu, ss, 2);
    ss += __shfl_xor_sync(0xffffffffu, ss, 1);
    if (lane == 0) sred[w] = ss;
    __syncthreads();
    float tot = sred[0] + sred[1] + sred[2] + sred[3];
    float scale = 1.f / fmaxf(sqrtf(tot), 1e-12f);
    val.x *= scale; val.y *= scale; val.z *= scale; val.w *= scale;
    v[tid] = val;
    if (tid == 0) atomicAdd(&g_bsq[row >> 6], tot * scale * scale);
}

// ================= K4: reduction GEMM (f32x2, dbl-buffered) =================
__global__ __launch_bounds__(256) void k_reduce(const float* __restrict__ red_w) {
    __shared__ float sW[32 * 68];
    __shared__ float sV[32 * 68];
    __shared__ float sBS[32];
    const int tid = threadIdx.x;
    const int o0 = blockIdx.x * 32;
    const int j0 = blockIdx.y * 4096;
    if (tid < 32) sBS[tid] = 1.f / fmaxf(sqrtf(g_bsq[tid]), 1e-12f);
    const int op = (tid & 15) * 2;
    const int bp = (tid >> 4) * 2;
    ull a00 = 0ULL, a01 = 0ULL, a10 = 0ULL, a11 = 0ULL;

    float rw[8], rv[8];
#pragma unroll
    for (int j = 0; j < 8; j++) {
        int idx = tid + j * 256, r = idx >> 6, jj = idx & 63;
        rw[j] = red_w[(size_t)(o0 + r) * KD + j0 + jj];
        rv[j] = g_vlad[(size_t)r * KD + j0 + jj];
    }
    for (int c = 0; c < 64; c++) {
        __syncthreads();
#pragma unroll
        for (int j = 0; j < 8; j++) {
            int idx = tid + j * 256, r = idx >> 6, jj = idx & 63;
            sW[r * 68 + jj] = rw[j];
            sV[r * 68 + jj] = rv[j] * sBS[r];
        }
        __syncthreads();
        if (c + 1 < 64) {
            int jc = j0 + (c + 1) * 64;
#pragma unroll
            for (int j = 0; j < 8; j++) {
                int idx = tid + j * 256, r = idx >> 6, jj = idx & 63;
                rw[j] = red_w[(size_t)(o0 + r) * KD + jc + jj];
                rv[j] = g_vlad[(size_t)r * KD + jc + jj];
            }
        }
        const ulonglong2* wp0 = (const ulonglong2*)(sW + op * 68);
        const ulonglong2* wp1 = (const ulonglong2*)(sW + (op + 1) * 68);
        const ulonglong2* vp0 = (const ulonglong2*)(sV + bp * 68);
        const ulonglong2* vp1 = (const ulonglong2*)(sV + (bp + 1) * 68);
#pragma unroll
        for (int q = 0; q < 16; q++) {
            ulonglong2 w0 = wp0[q], w1 = wp1[q];
            ulonglong2 v0 = vp0[q], v1 = vp1[q];
            fma2(a00, w0.x, v0.x); fma2(a00, w0.y, v0.y);
            fma2(a01, w0.x, v1.x); fma2(a01, w0.y, v1.y);
            fma2(a10, w1.x, v0.x); fma2(a10, w1.y, v0.y);
            fma2(a11, w1.x, v1.x); fma2(a11, w1.y, v1.y);
        }
    }
    float2 f00 = unpack2(a00), f01 = unpack2(a01), f10 = unpack2(a10), f11 = unpack2(a11);
    atomicAdd(&g_outpre[(size_t)bp * OUTN + o0 + op],           f00.x + f00.y);
    atomicAdd(&g_outpre[(size_t)(bp + 1) * OUTN + o0 + op],     f01.x + f01.y);
    atomicAdd(&g_outpre[(size_t)bp * OUTN + o0 + op + 1],       f10.x + f10.y);
    atomicAdd(&g_outpre[(size_t)(bp + 1) * OUTN + o0 + op + 1], f11.x + f11.y);
}

// ================= K5: LayerNorm =================
__global__ __launch_bounds__(256) void k_ln(
    const float* __restrict__ gamma, const float* __restrict__ beta,
    float* __restrict__ out)
{
    __shared__ float sred[8];
    const int b = blockIdx.x, tid = threadIdx.x, lane = tid & 31, w = tid >> 5;
    float4 v = ((const float4*)(g_outpre + (size_t)b * OUTN))[tid];
    float s = v.x + v.y + v.z + v.w;
    s += __shfl_xor_sync(0xffffffffu, s, 16);
    s += __shfl_xor_sync(0xffffffffu, s, 8);
    s += __shfl_xor_sync(0xffffffffu, s, 4);
    s += __shfl_xor_sync(0xffffffffu, s, 2);
    s += __shfl_xor_sync(0xffffffffu, s, 1);
    if (lane == 0) sred[w] = s;
    __syncthreads();
    float tot = 0.f;
#pragma unroll
    for (int i = 0; i < 8; i++) tot += sred[i];
    const float mu = tot * (1.f / 1024.f);
    float dx0 = v.x - mu, dx1 = v.y - mu, dx2 = v.z - mu, dx3 = v.w - mu;
    float vs = dx0 * dx0 + dx1 * dx1 + dx2 * dx2 + dx3 * dx3;
    vs += __shfl_xor_sync(0xffffffffu, vs, 16);
    vs += __shfl_xor_sync(0xffffffffu, vs, 8);
    vs += __shfl_xor_sync(0xffffffffu, vs, 4);
    vs += __shfl_xor_sync(0xffffffffu, vs, 2);
    vs += __shfl_xor_sync(0xffffffffu, vs, 1);
    __syncthreads();
    if (lane == 0) sred[w] = vs;
    __syncthreads();
    float vtot = 0.f;
#pragma unroll
    for (int i = 0; i < 8; i++) vtot += sred[i];
    const float inv = 1.f / sqrtf(vtot * (1.f / 1024.f) + 1e-5f);
    float4 gm = ((const float4*)gamma)[tid];
    float4 be = ((const float4*)beta)[tid];
    float4 r;
    r.x = dx0 * inv * gm.x + be.x;
    r.y = dx1 * inv * gm.y + be.y;
    r.z = dx2 * inv * gm.z + be.z;
    r.w = dx3 * inv * gm.w + be.w;
    ((float4*)(out + (size_t)b * OUTN))[tid] = r;
}

// ================= launch =================
extern "C" void kernel_launch(void* const* d_in, const int* in_sizes, int n_in,
                              void* d_out, int out_size)
{
    const float* x         = (const float*)d_in[0];
    const int*   mask      = (const int*)d_in[1];
    const float* centroids = (const float*)d_in[2];
    const float* conv_w    = (const float*)d_in[3];
    const float* red_w     = (const float*)d_in[4];
    const float* gamma     = (const float*)d_in[5];
    const float* beta      = (const float*)d_in[6];
    float* out = (float*)d_out;

    cudaFuncSetAttribute(k_g1, cudaFuncAttributeMaxDynamicSharedMemorySize, G1_SMEM);
    cudaFuncSetAttribute(k_g2, cudaFuncAttributeMaxDynamicSharedMemorySize, G2_SMEM);

    k_zero<<<128, 256>>>();
    k_wsplit<<<64, 512>>>(conv_w);
    k_transpose<<<dim3(BB, 98, 16), dim3(32, 8)>>>(x);
    k_g1<<<dim3(BB, 25), 256, G1_SMEM>>>(mask);
    k_g2<<<dim3(BB, 4), 256, G2_SMEM>>>(x, centroids);
    k_intranorm<<<BB * KK, 128>>>();
    k_reduce<<<dim3(32, 8), 256>>>(red_w);
    k_ln<<<BB, 256>>>(gamma, beta, out);
}

// round 7
// speedup vs baseline: 2.5747x; 1.2823x over previous
#include <cuda_runtime.h>
#include <cuda_bf16.h>
#include <math.h>
#include <cstdint>

#define BB 32
#define DD 512
#define TT 64
#define RR 49
#define TR 3136
#define KK 64
#define OUTN 1024
#define KD 32768

typedef unsigned long long ull;

// ================= mma / ldmatrix =================
__device__ __forceinline__ void mma_bf16(float* c, const uint32_t* a, const uint32_t* b) {
    asm volatile(
        "mma.sync.aligned.m16n8k16.row.col.f32.bf16.bf16.f32 "
        "{%0,%1,%2,%3}, {%4,%5,%6,%7}, {%8,%9}, {%0,%1,%2,%3};"
        : "+f"(c[0]), "+f"(c[1]), "+f"(c[2]), "+f"(c[3])
        : "r"(a[0]), "r"(a[1]), "r"(a[2]), "r"(a[3]), "r"(b[0]), "r"(b[1]));
}
__device__ __forceinline__ void ldmx4(uint32_t* r, uint32_t a) {
    asm volatile("ldmatrix.sync.aligned.m8n8.x4.shared.b16 {%0,%1,%2,%3}, [%4];"
                 : "=r"(r[0]), "=r"(r[1]), "=r"(r[2]), "=r"(r[3]) : "r"(a));
}
__device__ __forceinline__ void ldmx4t(uint32_t* r, uint32_t a) {
    asm volatile("ldmatrix.sync.aligned.m8n8.x4.trans.shared.b16 {%0,%1,%2,%3}, [%4];"
                 : "=r"(r[0]), "=r"(r[1]), "=r"(r[2]), "=r"(r[3]) : "r"(a));
}
__device__ __forceinline__ void ldmx2(uint32_t* r, uint32_t a) {
    asm volatile("ldmatrix.sync.aligned.m8n8.x2.shared.b16 {%0,%1}, [%2];"
                 : "=r"(r[0]), "=r"(r[1]) : "r"(a));
}
__device__ __forceinline__ uint32_t smem_u32(const void* p) {
    uint32_t a;
    asm("{ .reg .u64 t; cvta.to.shared.u64 t, %1; cvt.u32.u64 %0, t; }" : "=r"(a) : "l"(p));
    return a;
}
__device__ __forceinline__ void split_bf(float f, __nv_bfloat16& h, __nv_bfloat16& l) {
    h = __float2bfloat16(f);
    l = __float2bfloat16(f - __bfloat162float(h));
}
__device__ __forceinline__ uint32_t pkbf(__nv_bfloat16 a, __nv_bfloat16 b) {
    return (uint32_t)__bfloat16_as_ushort(a) | ((uint32_t)__bfloat16_as_ushort(b) << 16);
}

// ================= f32x2 helpers (k_reduce) =================
__device__ __forceinline__ void fma2(ull& d, ull a, ull b) {
    asm("fma.rn.f32x2 %0, %1, %2, %0;" : "+l"(d) : "l"(a), "l"(b));
}
__device__ __forceinline__ float2 unpack2(ull v) {
    float2 f; asm("mov.b64 {%0,%1}, %2;" : "=f"(f.x), "=f"(f.y) : "l"(v)); return f;
}

// ================= scratch =================
__device__ __align__(256) __nv_bfloat16 g_ass_hi[(size_t)BB * KK * TR];   // 12.8 MB
__device__ __align__(256) __nv_bfloat16 g_ass_lo[(size_t)BB * KK * TR];
__device__ __align__(256) float g_asum[BB * KK];
__device__ __align__(256) float g_vlad[BB * KD];          // 4 MB (accumulated)
__device__ __align__(256) float g_bsq[BB];
__device__ __align__(256) float g_outpre[BB * OUTN];

__global__ void k_zero() {
    int i = blockIdx.x * 256 + threadIdx.x;
    g_vlad[i] = 0.f;                       // grid sized to exactly BB*KD
    if (i < BB * OUTN) g_outpre[i] = 0.f;
    if (i < BB * KK)   g_asum[i]   = 0.f;
    if (i < BB)        g_bsq[i]    = 0.f;
}

extern __shared__ unsigned char smx[];

// ================= GEMM1: logits -> softmax -> assign + a_sum =================
// grid (32, 25), block 256 (8 warps). C tile [128 tr x 64 k]; K loop: d chunks of 64.
// x staged native [64 d][136 tr] bf16 hi/lo; A-frags via ldmatrix.trans.
#define X1ROW 136
#define W1ROW 72
#define G1_XH 0
#define G1_XL (64 * X1ROW)
#define G1_WH (2 * 64 * X1ROW)
#define G1_WL (2 * 64 * X1ROW + 64 * W1ROW)
#define G1_END (2 * 64 * X1ROW + 2 * 64 * W1ROW)
#define G1_SMEM (G1_END * 2 + 256)

__global__ __launch_bounds__(256) void k_g1(const float* __restrict__ x,
                                            const int* __restrict__ mask,
                                            const float* __restrict__ conv_w) {
    uint16_t* S = (uint16_t*)smx;
    float* sAs = (float*)(S + G1_END);
    const uint32_t sb = smem_u32(S);
    const int tid = threadIdx.x, wid = tid >> 5, lane = tid & 31;
    const int g = lane >> 2, t = lane & 3;
    const int b = blockIdx.x, tr0 = blockIdx.y * 128;

    if (tid < 64) sAs[tid] = 0.f;

    float cacc[8][4];
#pragma unroll
    for (int n = 0; n < 8; n++)
#pragma unroll
        for (int i = 0; i < 4; i++) cacc[n][i] = 0.f;

    // ldmatrix addresses (constant over chunks except s)
    const uint32_t aoff = (uint32_t)(((lane >> 4) * 8 + (lane & 7)) * X1ROW +
                                     wid * 16 + ((lane >> 3) & 1) * 8) * 2;
    const int L = lane & 15;
    const uint32_t boff = (uint32_t)((L & 7) * W1ROW + (L >> 3) * 8) * 2;

    for (int q = 0; q < 8; q++) {
        __syncthreads();
        // stage x chunk [64 d][128 tr] fp32 -> hi/lo bf16, native layout
        for (int u = tid; u < 2048; u += 256) {
            int row = u >> 5, c4 = u & 31;
            int trg = tr0 + c4 * 4;
            uint2 vh = {0u, 0u}, vl = {0u, 0u};
            if (trg < TR) {
                float4 xv = *(const float4*)(x + ((size_t)b * DD + q * 64 + row) * TR + trg);
                __nv_bfloat16 h0, l0, h1, l1, h2, l2, h3, l3;
                split_bf(xv.x, h0, l0); split_bf(xv.y, h1, l1);
                split_bf(xv.z, h2, l2); split_bf(xv.w, h3, l3);
                vh.x = pkbf(h0, h1); vh.y = pkbf(h2, h3);
                vl.x = pkbf(l0, l1); vl.y = pkbf(l2, l3);
            }
            *(uint2*)(S + G1_XH + row * X1ROW + c4 * 4) = vh;
            *(uint2*)(S + G1_XL + row * X1ROW + c4 * 4) = vl;
        }
        // stage W chunk [64 k][64 d] fp32 -> hi/lo
        for (int u = tid; u < 1024; u += 256) {
            int row = u >> 4, c4 = u & 15;
            float4 wv = *(const float4*)(conv_w + row * DD + q * 64 + c4 * 4);
            __nv_bfloat16 h0, l0, h1, l1, h2, l2, h3, l3;
            split_bf(wv.x, h0, l0); split_bf(wv.y, h1, l1);
            split_bf(wv.z, h2, l2); split_bf(wv.w, h3, l3);
            uint2 vh = { pkbf(h0, h1), pkbf(h2, h3) };
            uint2 vl = { pkbf(l0, l1), pkbf(l2, l3) };
            *(uint2*)(S + G1_WH + row * W1ROW + c4 * 4) = vh;
            *(uint2*)(S + G1_WL + row * W1ROW + c4 * 4) = vl;
        }
        __syncthreads();

#pragma unroll
        for (int s = 0; s < 4; s++) {
            uint32_t ah[4], al[4];
            ldmx4t(ah, sb + G1_XH * 2 + (uint32_t)(s * 16 * X1ROW) * 2 + aoff);
            ldmx4t(al, sb + G1_XL * 2 + (uint32_t)(s * 16 * X1ROW) * 2 + aoff);
#pragma unroll
            for (int n = 0; n < 8; n++) {
                uint32_t bh[2], bl[2];
                uint32_t bb = (uint32_t)(n * 8 * W1ROW + s * 16) * 2 + boff;
                ldmx2(bh, sb + G1_WH * 2 + bb);
                ldmx2(bl, sb + G1_WL * 2 + bb);
                mma_bf16(cacc[n], ah, bh);
                mma_bf16(cacc[n], ah, bl);
                mma_bf16(cacc[n], al, bh);
            }
        }
    }

    // epilogue: rows tra = tr0+wid*16+g, trb = tra+8; cols k = n*8+2t+{0,1}
    const int tra = tr0 + wid * 16 + g;
    const int trb = tra + 8;
    float ma = -1e30f, mb = -1e30f;
#pragma unroll
    for (int n = 0; n < 8; n++) {
        ma = fmaxf(ma, fmaxf(cacc[n][0], cacc[n][1]));
        mb = fmaxf(mb, fmaxf(cacc[n][2], cacc[n][3]));
    }
    ma = fmaxf(ma, __shfl_xor_sync(0xffffffffu, ma, 1));
    ma = fmaxf(ma, __shfl_xor_sync(0xffffffffu, ma, 2));
    mb = fmaxf(mb, __shfl_xor_sync(0xffffffffu, mb, 1));
    mb = fmaxf(mb, __shfl_xor_sync(0xffffffffu, mb, 2));
    float sa = 0.f, sb2 = 0.f;
#pragma unroll
    for (int n = 0; n < 8; n++) {
        cacc[n][0] = __expf(cacc[n][0] - ma); sa += cacc[n][0];
        cacc[n][1] = __expf(cacc[n][1] - ma); sa += cacc[n][1];
        cacc[n][2] = __expf(cacc[n][2] - mb); sb2 += cacc[n][2];
        cacc[n][3] = __expf(cacc[n][3] - mb); sb2 += cacc[n][3];
    }
    sa  += __shfl_xor_sync(0xffffffffu, sa, 1);
    sa  += __shfl_xor_sync(0xffffffffu, sa, 2);
    sb2 += __shfl_xor_sync(0xffffffffu, sb2, 1);
    sb2 += __shfl_xor_sync(0xffffffffu, sb2, 2);
    const float mva = (tra < TR) ? (float)mask[b * TT + tra / RR] : 0.f;
    const float mvb = (trb < TR) ? (float)mask[b * TT + trb / RR] : 0.f;
    const float inva = mva / sa, invb = mvb / sb2;

#pragma unroll
    for (int n = 0; n < 8; n++) {
#pragma unroll
        for (int i = 0; i < 2; i++) {
            const int k = n * 8 + 2 * t + i;
            float aa = cacc[n][i] * inva;
            float ab = cacc[n][2 + i] * invb;
            if (tra < TR) {
                __nv_bfloat16 h, l; split_bf(aa, h, l);
                size_t o = ((size_t)b * KK + k) * TR + tra;
                g_ass_hi[o] = h; g_ass_lo[o] = l;
            }
            if (trb < TR) {
                __nv_bfloat16 h, l; split_bf(ab, h, l);
                size_t o = ((size_t)b * KK + k) * TR + trb;
                g_ass_hi[o] = h; g_ass_lo[o] = l;
            }
            float sum = aa + ab;
            sum += __shfl_xor_sync(0xffffffffu, sum, 4);
            sum += __shfl_xor_sync(0xffffffffu, sum, 8);
            sum += __shfl_xor_sync(0xffffffffu, sum, 16);
            if (g == 0) atomicAdd(&sAs[k], sum);
        }
    }
    __syncthreads();
    if (tid < 64) atomicAdd(&g_asum[b * 64 + tid], sAs[tid]);
}

// ================= GEMM2: vlad_partial[b,k,d] += sum_tr a*x =================
// grid (32, 4, 4), block 256. C tile [128 d x 64 k]; K = tr chunks (split 4 ways).
#define X2ROW 72
#define G2_XH 0
#define G2_XL (128 * X2ROW)
#define G2_AH (2 * 128 * X2ROW)
#define G2_AL (2 * 128 * X2ROW + 64 * X2ROW)
#define G2_END (2 * 128 * X2ROW + 2 * 64 * X2ROW)
#define G2_SMEM (G2_END * 2 + 256)

__global__ __launch_bounds__(256) void k_g2(const float* __restrict__ x) {
    uint16_t* S = (uint16_t*)smx;
    const uint32_t sbb = smem_u32(S);
    const int tid = threadIdx.x, wid = tid >> 5, lane = tid & 31;
    const int g = lane >> 2, t = lane & 3;
    const int b = blockIdx.x, d0 = blockIdx.y * 128, sp = blockIdx.z;
    const int c0 = sp ? 12 * sp + 1 : 0;
    const int c1 = (sp == 3) ? 49 : 12 * (sp + 1) + 1;

    float cacc[8][4];
#pragma unroll
    for (int n = 0; n < 8; n++)
#pragma unroll
        for (int i = 0; i < 4; i++) cacc[n][i] = 0.f;

    const uint32_t aoff = (uint32_t)((wid * 16 + (lane & 15)) * X2ROW + (lane >> 4) * 8) * 2;
    const int L = lane & 15;
    const uint32_t boff = (uint32_t)((L & 7) * X2ROW + (L >> 3) * 8) * 2;

    for (int c = c0; c < c1; c++) {
        const int trc = c * 64;
        __syncthreads();
        for (int u = tid; u < 2048; u += 256) {     // x chunk [128 d][64 tr]
            int row = u >> 4, c4 = u & 15;
            float4 xv = *(const float4*)(x + ((size_t)b * DD + d0 + row) * TR + trc + c4 * 4);
            __nv_bfloat16 h0, l0, h1, l1, h2, l2, h3, l3;
            split_bf(xv.x, h0, l0); split_bf(xv.y, h1, l1);
            split_bf(xv.z, h2, l2); split_bf(xv.w, h3, l3);
            uint2 vh = { pkbf(h0, h1), pkbf(h2, h3) };
            uint2 vl = { pkbf(l0, l1), pkbf(l2, l3) };
            *(uint2*)(S + G2_XH + row * X2ROW + c4 * 4) = vh;
            *(uint2*)(S + G2_XL + row * X2ROW + c4 * 4) = vl;
        }
        for (int u = tid; u < 512; u += 256) {      // assign chunk [64 k][64 tr]
            int row = u >> 3, c8 = u & 7;
            size_t src = ((size_t)b * KK + row) * TR + trc + c8 * 8;
            uint4 vh = *(const uint4*)(g_ass_hi + src);
            uint4 vl = *(const uint4*)(g_ass_lo + src);
            *(uint2*)(S + G2_AH + row * X2ROW + c8 * 8)     = make_uint2(vh.x, vh.y);
            *(uint2*)(S + G2_AH + row * X2ROW + c8 * 8 + 4) = make_uint2(vh.z, vh.w);
            *(uint2*)(S + G2_AL + row * X2ROW + c8 * 8)     = make_uint2(vl.x, vl.y);
            *(uint2*)(S + G2_AL + row * X2ROW + c8 * 8 + 4) = make_uint2(vl.z, vl.w);
        }
        __syncthreads();

#pragma unroll
        for (int s = 0; s < 4; s++) {
            uint32_t ah[4], al[4];
            ldmx4(ah, sbb + G2_XH * 2 + (uint32_t)(s * 16) * 2 + aoff);
            ldmx4(al, sbb + G2_XL * 2 + (uint32_t)(s * 16) * 2 + aoff);
#pragma unroll
            for (int n = 0; n < 8; n++) {
                uint32_t bh[2], bl[2];
                uint32_t bb = (uint32_t)(n * 8 * X2ROW + s * 16) * 2 + boff;
                ldmx2(bh, sbb + G2_AH * 2 + bb);
                ldmx2(bl, sbb + G2_AL * 2 + bb);
                mma_bf16(cacc[n], ah, bh);
                mma_bf16(cacc[n], ah, bl);
                mma_bf16(cacc[n], al, bh);
            }
        }
    }

    const int da = d0 + wid * 16 + g;
    const int db = da + 8;
#pragma unroll
    for (int n = 0; n < 8; n++) {
#pragma unroll
        for (int i = 0; i < 2; i++) {
            const int k = n * 8 + 2 * t + i;
            atomicAdd(&g_vlad[((size_t)b * KK + k) * DD + da], cacc[n][i]);
            atomicAdd(&g_vlad[((size_t)b * KK + k) * DD + db], cacc[n][2 + i]);
        }
    }
}

// ================= K3: subtract a_sum*centroid, intra-norm, per-b sumsq =================
__global__ __launch_bounds__(128) void k_intranorm(const float* __restrict__ centroids) {
    __shared__ float sred[4];
    const int row = blockIdx.x;            // b*64 + k
    const int tid = threadIdx.x, lane = tid & 31, w = tid >> 5;
    const float as = g_asum[row];
    float4* v = (float4*)(g_vlad + (size_t)row * 512);
    float4 val = v[tid];
    const float4 cv = ((const float4*)(centroids + (size_t)(row & 63) * DD))[tid];
    val.x -= as * cv.x; val.y -= as * cv.y; val.z -= as * cv.z; val.w -= as * cv.w;
    float ss = val.x * val.x + val.y * val.y + val.z * val.z + val.w * val.w;
    ss += __shfl_xor_sync(0xffffffffu, ss, 16);
    ss += __shfl_xor_sync(0xffffffffu, ss, 8);
    ss += __shfl_xor_sync(0xffffffffu, ss, 4);
    ss += __shfl_xor_sync(0xffffffffu, ss, 2);
    ss += __shfl_xor_sync(0xffffffffu, ss, 1);
    if (lane == 0) sred[w] = ss;
    __syncthreads();
    float tot = sred[0] + sred[1] + sred[2] + sred[3];
    float scale = 1.f / fmaxf(sqrtf(tot), 1e-12f);
    val.x *= scale; val.y *= scale; val.z *= scale; val.w *= scale;
    v[tid] = val;
    if (tid == 0) atomicAdd(&g_bsq[row >> 6], tot * scale * scale);
}

// ================= K4: reduction GEMM (f32x2, dbl-buffered) =================
__global__ __launch_bounds__(256) void k_reduce(const float* __restrict__ red_w) {
    __shared__ float sW[32 * 68];
    __shared__ float sV[32 * 68];
    __shared__ float sBS[32];
    const int tid = threadIdx.x;
    const int o0 = blockIdx.x * 32;
    const int j0 = blockIdx.y * 4096;
    if (tid < 32) sBS[tid] = 1.f / fmaxf(sqrtf(g_bsq[tid]), 1e-12f);
    const int op = (tid & 15) * 2;
    const int bp = (tid >> 4) * 2;
    ull a00 = 0ULL, a01 = 0ULL, a10 = 0ULL, a11 = 0ULL;

    float rw[8], rv[8];
#pragma unroll
    for (int j = 0; j < 8; j++) {
        int idx = tid + j * 256, r = idx >> 6, jj = idx & 63;
        rw[j] = red_w[(size_t)(o0 + r) * KD + j0 + jj];
        rv[j] = g_vlad[(size_t)r * KD + j0 + jj];
    }
    for (int c = 0; c < 64; c++) {
        __syncthreads();
#pragma unroll
        for (int j = 0; j < 8; j++) {
            int idx = tid + j * 256, r = idx >> 6, jj = idx & 63;
            sW[r * 68 + jj] = rw[j];
            sV[r * 68 + jj] = rv[j] * sBS[r];
        }
        __syncthreads();
        if (c + 1 < 64) {
            int jc = j0 + (c + 1) * 64;
#pragma unroll
            for (int j = 0; j < 8; j++) {
                int idx = tid + j * 256, r = idx >> 6, jj = idx & 63;
                rw[j] = red_w[(size_t)(o0 + r) * KD + jc + jj];
                rv[j] = g_vlad[(size_t)r * KD + jc + jj];
            }
        }
        const ulonglong2* wp0 = (const ulonglong2*)(sW + op * 68);
        const ulonglong2* wp1 = (const ulonglong2*)(sW + (op + 1) * 68);
        const ulonglong2* vp0 = (const ulonglong2*)(sV + bp * 68);
        const ulonglong2* vp1 = (const ulonglong2*)(sV + (bp + 1) * 68);
#pragma unroll
        for (int q = 0; q < 16; q++) {
            ulonglong2 w0 = wp0[q], w1 = wp1[q];
            ulonglong2 v0 = vp0[q], v1 = vp1[q];
            fma2(a00, w0.x, v0.x); fma2(a00, w0.y, v0.y);
            fma2(a01, w0.x, v1.x); fma2(a01, w0.y, v1.y);
            fma2(a10, w1.x, v0.x); fma2(a10, w1.y, v0.y);
            fma2(a11, w1.x, v1.x); fma2(a11, w1.y, v1.y);
        }
    }
    float2 f00 = unpack2(a00), f01 = unpack2(a01), f10 = unpack2(a10), f11 = unpack2(a11);
    atomicAdd(&g_outpre[(size_t)bp * OUTN + o0 + op],           f00.x + f00.y);
    atomicAdd(&g_outpre[(size_t)(bp + 1) * OUTN + o0 + op],     f01.x + f01.y);
    atomicAdd(&g_outpre[(size_t)bp * OUTN + o0 + op + 1],       f10.x + f10.y);
    atomicAdd(&g_outpre[(size_t)(bp + 1) * OUTN + o0 + op + 1], f11.x + f11.y);
}

// ================= K5: LayerNorm =================
__global__ __launch_bounds__(256) void k_ln(
    const float* __restrict__ gamma, const float* __restrict__ beta,
    float* __restrict__ out)
{
    __shared__ float sred[8];
    const int b = blockIdx.x, tid = threadIdx.x, lane = tid & 31, w = tid >> 5;
    float4 v = ((const float4*)(g_outpre + (size_t)b * OUTN))[tid];
    float s = v.x + v.y + v.z + v.w;
    s += __shfl_xor_sync(0xffffffffu, s, 16);
    s += __shfl_xor_sync(0xffffffffu, s, 8);
    s += __shfl_xor_sync(0xffffffffu, s, 4);
    s += __shfl_xor_sync(0xffffffffu, s, 2);
    s += __shfl_xor_sync(0xffffffffu, s, 1);
    if (lane == 0) sred[w] = s;
    __syncthreads();
    float tot = 0.f;
#pragma unroll
    for (int i = 0; i < 8; i++) tot += sred[i];
    const float mu = tot * (1.f / 1024.f);
    float dx0 = v.x - mu, dx1 = v.y - mu, dx2 = v.z - mu, dx3 = v.w - mu;
    float vs = dx0 * dx0 + dx1 * dx1 + dx2 * dx2 + dx3 * dx3;
    vs += __shfl_xor_sync(0xffffffffu, vs, 16);
    vs += __shfl_xor_sync(0xffffffffu, vs, 8);
    vs += __shfl_xor_sync(0xffffffffu, vs, 4);
    vs += __shfl_xor_sync(0xffffffffu, vs, 2);
    vs += __shfl_xor_sync(0xffffffffu, vs, 1);
    __syncthreads();
    if (lane == 0) sred[w] = vs;
    __syncthreads();
    float vtot = 0.f;
#pragma unroll
    for (int i = 0; i < 8; i++) vtot += sred[i];
    const float inv = 1.f / sqrtf(vtot * (1.f / 1024.f) + 1e-5f);
    float4 gm = ((const float4*)gamma)[tid];
    float4 be = ((const float4*)beta)[tid];
    float4 r;
    r.x = dx0 * inv * gm.x + be.x;
    r.y = dx1 * inv * gm.y + be.y;
    r.z = dx2 * inv * gm.z + be.z;
    r.w = dx3 * inv * gm.w + be.w;
    ((float4*)(out + (size_t)b * OUTN))[tid] = r;
}

// ================= launch =================
extern "C" void kernel_launch(void* const* d_in, const int* in_sizes, int n_in,
                              void* d_out, int out_size)
{
    const float* x         = (const float*)d_in[0];
    const int*   mask      = (const int*)d_in[1];
    const float* centroids = (const float*)d_in[2];
    const float* conv_w    = (const float*)d_in[3];
    const float* red_w     = (const float*)d_in[4];
    const float* gamma     = (const float*)d_in[5];
    const float* beta      = (const float*)d_in[6];
    float* out = (float*)d_out;

    cudaFuncSetAttribute(k_g1, cudaFuncAttributeMaxDynamicSharedMemorySize, G1_SMEM);
    cudaFuncSetAttribute(k_g2, cudaFuncAttributeMaxDynamicSharedMemorySize, G2_SMEM);

    k_zero<<<BB * KD / 256, 256>>>();
    k_g1<<<dim3(BB, 25), 256, G1_SMEM>>>(x, mask, conv_w);
    k_g2<<<dim3(BB, 4, 4), 256, G2_SMEM>>>(x);
    k_intranorm<<<BB * KK, 128>>>(centroids);
    k_reduce<<<dim3(32, 8), 256>>>(red_w);
    k_ln<<<BB, 256>>>(gamma, beta, out);
}

// round 8
// speedup vs baseline: 3.0043x; 1.1669x over previous
#include <cuda_runtime.h>
#include <cuda_bf16.h>
#include <math.h>
#include <cstdint>

#define BB 32
#define DD 512
#define TT 64
#define RR 49
#define TR 3136
#define KK 64
#define OUTN 1024
#define KD 32768

// ================= mma / ldmatrix =================
__device__ __forceinline__ void mma_bf16(float* c, const uint32_t* a, const uint32_t* b) {
    asm volatile(
        "mma.sync.aligned.m16n8k16.row.col.f32.bf16.bf16.f32 "
        "{%0,%1,%2,%3}, {%4,%5,%6,%7}, {%8,%9}, {%0,%1,%2,%3};"
        : "+f"(c[0]), "+f"(c[1]), "+f"(c[2]), "+f"(c[3])
        : "r"(a[0]), "r"(a[1]), "r"(a[2]), "r"(a[3]), "r"(b[0]), "r"(b[1]));
}
__device__ __forceinline__ void ldmx4(uint32_t* r, uint32_t a) {
    asm volatile("ldmatrix.sync.aligned.m8n8.x4.shared.b16 {%0,%1,%2,%3}, [%4];"
                 : "=r"(r[0]), "=r"(r[1]), "=r"(r[2]), "=r"(r[3]) : "r"(a));
}
__device__ __forceinline__ void ldmx4t(uint32_t* r, uint32_t a) {
    asm volatile("ldmatrix.sync.aligned.m8n8.x4.trans.shared.b16 {%0,%1,%2,%3}, [%4];"
                 : "=r"(r[0]), "=r"(r[1]), "=r"(r[2]), "=r"(r[3]) : "r"(a));
}
__device__ __forceinline__ void ldmx2(uint32_t* r, uint32_t a) {
    asm volatile("ldmatrix.sync.aligned.m8n8.x2.shared.b16 {%0,%1}, [%2];"
                 : "=r"(r[0]), "=r"(r[1]) : "r"(a));
}
__device__ __forceinline__ uint32_t smem_u32(const void* p) {
    uint32_t a;
    asm("{ .reg .u64 t; cvta.to.shared.u64 t, %1; cvt.u32.u64 %0, t; }" : "=r"(a) : "l"(p));
    return a;
}
__device__ __forceinline__ void split_bf(float f, __nv_bfloat16& h, __nv_bfloat16& l) {
    h = __float2bfloat16(f);
    l = __float2bfloat16(f - __bfloat162float(h));
}
__device__ __forceinline__ uint32_t pkbf(__nv_bfloat16 a, __nv_bfloat16 b) {
    return (uint32_t)__bfloat16_as_ushort(a) | ((uint32_t)__bfloat16_as_ushort(b) << 16);
}

// ================= scratch =================
__device__ __align__(256) __nv_bfloat16 g_ass_hi[(size_t)BB * KK * TR];   // 12.8 MB
__device__ __align__(256) __nv_bfloat16 g_ass_lo[(size_t)BB * KK * TR];
__device__ __align__(256) float g_asum[BB * KK];
__device__ __align__(256) float g_vlad[BB * KD];          // 4 MB (accumulated)
__device__ __align__(256) float g_bsq[BB];
__device__ __align__(256) float g_outpre[BB * OUTN];

__global__ void k_zero() {
    int i = blockIdx.x * 256 + threadIdx.x;
    g_vlad[i] = 0.f;                       // grid sized to exactly BB*KD
    if (i < BB * OUTN) g_outpre[i] = 0.f;
    if (i < BB * KK)   g_asum[i]   = 0.f;
    if (i < BB)        g_bsq[i]    = 0.f;
}

extern __shared__ unsigned char smx[];

// ================= GEMM1: logits -> softmax -> assign + a_sum =================
// grid (32, 25), block 256 (8 warps). C tile [128 tr x 64 k]; K loop: d chunks of 64.
#define X1ROW 136
#define W1ROW 72
#define G1_XH 0
#define G1_XL (64 * X1ROW)
#define G1_WH (2 * 64 * X1ROW)
#define G1_WL (2 * 64 * X1ROW + 64 * W1ROW)
#define G1_END (2 * 64 * X1ROW + 2 * 64 * W1ROW)
#define G1_SMEM (G1_END * 2 + 256)

__global__ __launch_bounds__(256) void k_g1(const float* __restrict__ x,
                                            const int* __restrict__ mask,
                                            const float* __restrict__ conv_w) {
    uint16_t* S = (uint16_t*)smx;
    float* sAs = (float*)(S + G1_END);
    const uint32_t sb = smem_u32(S);
    const int tid = threadIdx.x, wid = tid >> 5, lane = tid & 31;
    const int g = lane >> 2, t = lane & 3;
    const int b = blockIdx.x, tr0 = blockIdx.y * 128;

    if (tid < 64) sAs[tid] = 0.f;

    float cacc[8][4];
#pragma unroll
    for (int n = 0; n < 8; n++)
#pragma unroll
        for (int i = 0; i < 4; i++) cacc[n][i] = 0.f;

    const uint32_t aoff = (uint32_t)(((lane >> 4) * 8 + (lane & 7)) * X1ROW +
                                     wid * 16 + ((lane >> 3) & 1) * 8) * 2;
    const int L = lane & 15;
    const uint32_t boff = (uint32_t)((L & 7) * W1ROW + (L >> 3) * 8) * 2;

    for (int q = 0; q < 8; q++) {
        __syncthreads();
        for (int u = tid; u < 2048; u += 256) {
            int row = u >> 5, c4 = u & 31;
            int trg = tr0 + c4 * 4;
            uint2 vh = {0u, 0u}, vl = {0u, 0u};
            if (trg < TR) {
                float4 xv = *(const float4*)(x + ((size_t)b * DD + q * 64 + row) * TR + trg);
                __nv_bfloat16 h0, l0, h1, l1, h2, l2, h3, l3;
                split_bf(xv.x, h0, l0); split_bf(xv.y, h1, l1);
                split_bf(xv.z, h2, l2); split_bf(xv.w, h3, l3);
                vh.x = pkbf(h0, h1); vh.y = pkbf(h2, h3);
                vl.x = pkbf(l0, l1); vl.y = pkbf(l2, l3);
            }
            *(uint2*)(S + G1_XH + row * X1ROW + c4 * 4) = vh;
            *(uint2*)(S + G1_XL + row * X1ROW + c4 * 4) = vl;
        }
        for (int u = tid; u < 1024; u += 256) {
            int row = u >> 4, c4 = u & 15;
            float4 wv = *(const float4*)(conv_w + row * DD + q * 64 + c4 * 4);
            __nv_bfloat16 h0, l0, h1, l1, h2, l2, h3, l3;
            split_bf(wv.x, h0, l0); split_bf(wv.y, h1, l1);
            split_bf(wv.z, h2, l2); split_bf(wv.w, h3, l3);
            uint2 vh = { pkbf(h0, h1), pkbf(h2, h3) };
            uint2 vl = { pkbf(l0, l1), pkbf(l2, l3) };
            *(uint2*)(S + G1_WH + row * W1ROW + c4 * 4) = vh;
            *(uint2*)(S + G1_WL + row * W1ROW + c4 * 4) = vl;
        }
        __syncthreads();

#pragma unroll
        for (int s = 0; s < 4; s++) {
            uint32_t ah[4], al[4];
            ldmx4t(ah, sb + G1_XH * 2 + (uint32_t)(s * 16 * X1ROW) * 2 + aoff);
            ldmx4t(al, sb + G1_XL * 2 + (uint32_t)(s * 16 * X1ROW) * 2 + aoff);
#pragma unroll
            for (int n = 0; n < 8; n++) {
                uint32_t bh[2], bl[2];
                uint32_t bb = (uint32_t)(n * 8 * W1ROW + s * 16) * 2 + boff;
                ldmx2(bh, sb + G1_WH * 2 + bb);
                ldmx2(bl, sb + G1_WL * 2 + bb);
                mma_bf16(cacc[n], ah, bh);
                mma_bf16(cacc[n], ah, bl);
                mma_bf16(cacc[n], al, bh);
            }
        }
    }

    const int tra = tr0 + wid * 16 + g;
    const int trb = tra + 8;
    float ma = -1e30f, mb = -1e30f;
#pragma unroll
    for (int n = 0; n < 8; n++) {
        ma = fmaxf(ma, fmaxf(cacc[n][0], cacc[n][1]));
        mb = fmaxf(mb, fmaxf(cacc[n][2], cacc[n][3]));
    }
    ma = fmaxf(ma, __shfl_xor_sync(0xffffffffu, ma, 1));
    ma = fmaxf(ma, __shfl_xor_sync(0xffffffffu, ma, 2));
    mb = fmaxf(mb, __shfl_xor_sync(0xffffffffu, mb, 1));
    mb = fmaxf(mb, __shfl_xor_sync(0xffffffffu, mb, 2));
    float sa = 0.f, sb2 = 0.f;
#pragma unroll
    for (int n = 0; n < 8; n++) {
        cacc[n][0] = __expf(cacc[n][0] - ma); sa += cacc[n][0];
        cacc[n][1] = __expf(cacc[n][1] - ma); sa += cacc[n][1];
        cacc[n][2] = __expf(cacc[n][2] - mb); sb2 += cacc[n][2];
        cacc[n][3] = __expf(cacc[n][3] - mb); sb2 += cacc[n][3];
    }
    sa  += __shfl_xor_sync(0xffffffffu, sa, 1);
    sa  += __shfl_xor_sync(0xffffffffu, sa, 2);
    sb2 += __shfl_xor_sync(0xffffffffu, sb2, 1);
    sb2 += __shfl_xor_sync(0xffffffffu, sb2, 2);
    const float mva = (tra < TR) ? (float)mask[b * TT + tra / RR] : 0.f;
    const float mvb = (trb < TR) ? (float)mask[b * TT + trb / RR] : 0.f;
    const float inva = mva / sa, invb = mvb / sb2;

#pragma unroll
    for (int n = 0; n < 8; n++) {
#pragma unroll
        for (int i = 0; i < 2; i++) {
            const int k = n * 8 + 2 * t + i;
            float aa = cacc[n][i] * inva;
            float ab = cacc[n][2 + i] * invb;
            if (tra < TR) {
                __nv_bfloat16 h, l; split_bf(aa, h, l);
                size_t o = ((size_t)b * KK + k) * TR + tra;
                g_ass_hi[o] = h; g_ass_lo[o] = l;
            }
            if (trb < TR) {
                __nv_bfloat16 h, l; split_bf(ab, h, l);
                size_t o = ((size_t)b * KK + k) * TR + trb;
                g_ass_hi[o] = h; g_ass_lo[o] = l;
            }
            float sum = aa + ab;
            sum += __shfl_xor_sync(0xffffffffu, sum, 4);
            sum += __shfl_xor_sync(0xffffffffu, sum, 8);
            sum += __shfl_xor_sync(0xffffffffu, sum, 16);
            if (g == 0) atomicAdd(&sAs[k], sum);
        }
    }
    __syncthreads();
    if (tid < 64) atomicAdd(&g_asum[b * 64 + tid], sAs[tid]);
}

// ================= GEMM2: vlad_partial[b,k,d] += sum_tr a*x =================
#define X2ROW 72
#define G2_XH 0
#define G2_XL (128 * X2ROW)
#define G2_AH (2 * 128 * X2ROW)
#define G2_AL (2 * 128 * X2ROW + 64 * X2ROW)
#define G2_END (2 * 128 * X2ROW + 2 * 64 * X2ROW)
#define G2_SMEM (G2_END * 2 + 256)

__global__ __launch_bounds__(256) void k_g2(const float* __restrict__ x) {
    uint16_t* S = (uint16_t*)smx;
    const uint32_t sbb = smem_u32(S);
    const int tid = threadIdx.x, wid = tid >> 5, lane = tid & 31;
    const int g = lane >> 2, t = lane & 3;
    const int b = blockIdx.x, d0 = blockIdx.y * 128, sp = blockIdx.z;
    const int c0 = sp ? 12 * sp + 1 : 0;
    const int c1 = (sp == 3) ? 49 : 12 * (sp + 1) + 1;

    float cacc[8][4];
#pragma unroll
    for (int n = 0; n < 8; n++)
#pragma unroll
        for (int i = 0; i < 4; i++) cacc[n][i] = 0.f;

    const uint32_t aoff = (uint32_t)((wid * 16 + (lane & 15)) * X2ROW + (lane >> 4) * 8) * 2;
    const int L = lane & 15;
    const uint32_t boff = (uint32_t)((L & 7) * X2ROW + (L >> 3) * 8) * 2;

    for (int c = c0; c < c1; c++) {
        const int trc = c * 64;
        __syncthreads();
        for (int u = tid; u < 2048; u += 256) {     // x chunk [128 d][64 tr]
            int row = u >> 4, c4 = u & 15;
            float4 xv = *(const float4*)(x + ((size_t)b * DD + d0 + row) * TR + trc + c4 * 4);
            __nv_bfloat16 h0, l0, h1, l1, h2, l2, h3, l3;
            split_bf(xv.x, h0, l0); split_bf(xv.y, h1, l1);
            split_bf(xv.z, h2, l2); split_bf(xv.w, h3, l3);
            uint2 vh = { pkbf(h0, h1), pkbf(h2, h3) };
            uint2 vl = { pkbf(l0, l1), pkbf(l2, l3) };
            *(uint2*)(S + G2_XH + row * X2ROW + c4 * 4) = vh;
            *(uint2*)(S + G2_XL + row * X2ROW + c4 * 4) = vl;
        }
        for (int u = tid; u < 512; u += 256) {      // assign chunk [64 k][64 tr]
            int row = u >> 3, c8 = u & 7;
            size_t src = ((size_t)b * KK + row) * TR + trc + c8 * 8;
            uint4 vh = *(const uint4*)(g_ass_hi + src);
            uint4 vl = *(const uint4*)(g_ass_lo + src);
            *(uint2*)(S + G2_AH + row * X2ROW + c8 * 8)     = make_uint2(vh.x, vh.y);
            *(uint2*)(S + G2_AH + row * X2ROW + c8 * 8 + 4) = make_uint2(vh.z, vh.w);
            *(uint2*)(S + G2_AL + row * X2ROW + c8 * 8)     = make_uint2(vl.x, vl.y);
            *(uint2*)(S + G2_AL + row * X2ROW + c8 * 8 + 4) = make_uint2(vl.z, vl.w);
        }
        __syncthreads();

#pragma unroll
        for (int s = 0; s < 4; s++) {
            uint32_t ah[4], al[4];
            ldmx4(ah, sbb + G2_XH * 2 + (uint32_t)(s * 16) * 2 + aoff);
            ldmx4(al, sbb + G2_XL * 2 + (uint32_t)(s * 16) * 2 + aoff);
#pragma unroll
            for (int n = 0; n < 8; n++) {
                uint32_t bh[2], bl[2];
                uint32_t bb = (uint32_t)(n * 8 * X2ROW + s * 16) * 2 + boff;
                ldmx2(bh, sbb + G2_AH * 2 + bb);
                ldmx2(bl, sbb + G2_AL * 2 + bb);
                mma_bf16(cacc[n], ah, bh);
                mma_bf16(cacc[n], ah, bl);
                mma_bf16(cacc[n], al, bh);
            }
        }
    }

    const int da = d0 + wid * 16 + g;
    const int db = da + 8;
#pragma unroll
    for (int n = 0; n < 8; n++) {
#pragma unroll
        for (int i = 0; i < 2; i++) {
            const int k = n * 8 + 2 * t + i;
            atomicAdd(&g_vlad[((size_t)b * KK + k) * DD + da], cacc[n][i]);
            atomicAdd(&g_vlad[((size_t)b * KK + k) * DD + db], cacc[n][2 + i]);
        }
    }
}

// ================= K3: subtract a_sum*centroid, intra-norm, per-b sumsq =================
__global__ __launch_bounds__(128) void k_intranorm(const float* __restrict__ centroids) {
    __shared__ float sred[4];
    const int row = blockIdx.x;            // b*64 + k
    const int tid = threadIdx.x, lane = tid & 31, w = tid >> 5;
    const float as = g_asum[row];
    float4* v = (float4*)(g_vlad + (size_t)row * 512);
    float4 val = v[tid];
    const float4 cv = ((const float4*)(centroids + (size_t)(row & 63) * DD))[tid];
    val.x -= as * cv.x; val.y -= as * cv.y; val.z -= as * cv.z; val.w -= as * cv.w;
    float ss = val.x * val.x + val.y * val.y + val.z * val.z + val.w * val.w;
    ss += __shfl_xor_sync(0xffffffffu, ss, 16);
    ss += __shfl_xor_sync(0xffffffffu, ss, 8);
    ss += __shfl_xor_sync(0xffffffffu, ss, 4);
    ss += __shfl_xor_sync(0xffffffffu, ss, 2);
    ss += __shfl_xor_sync(0xffffffffu, ss, 1);
    if (lane == 0) sred[w] = ss;
    __syncthreads();
    float tot = sred[0] + sred[1] + sred[2] + sred[3];
    float scale = 1.f / fmaxf(sqrtf(tot), 1e-12f);
    val.x *= scale; val.y *= scale; val.z *= scale; val.w *= scale;
    v[tid] = val;
    if (tid == 0) atomicAdd(&g_bsq[row >> 6], tot * scale * scale);
}

// ================= K4: reduction GEMM on HMMA (split-bf16, inline conversion) =================
// M=o (1024), N=b (32), K=j (32768). grid (16 o-tiles of 64, 16 j-splits of 2048), block 256.
// Warp tile: 16 o x 16 b (two n8). Both operands K-contiguous -> same frag scheme as k_g2.
#define RROW 72
__global__ __launch_bounds__(256) void k_reduce(const float* __restrict__ red_w) {
    __shared__ uint16_t WH[64 * RROW], WL[64 * RROW];
    __shared__ uint16_t VH[32 * RROW], VL[32 * RROW];
    __shared__ float sBS[32];
    const int tid = threadIdx.x, wid = tid >> 5, lane = tid & 31;
    const int g = lane >> 2, t = lane & 3;
    const int o0 = blockIdx.x * 64;
    const int j0 = blockIdx.y * 2048;
    const int warp_m = (wid & 3) * 16;
    const int warp_n = (wid >> 2) * 16;

    if (tid < 32) sBS[tid] = 1.f / fmaxf(sqrtf(g_bsq[tid]), 1e-12f);

    float cacc[2][4];
#pragma unroll
    for (int n = 0; n < 2; n++)
#pragma unroll
        for (int i = 0; i < 4; i++) cacc[n][i] = 0.f;

    const uint32_t whb = smem_u32(WH), wlb = smem_u32(WL);
    const uint32_t vhb = smem_u32(VH), vlb = smem_u32(VL);
    const uint32_t aoff = (uint32_t)((warp_m + (lane & 15)) * RROW + (lane >> 4) * 8) * 2;
    const uint32_t boff = (uint32_t)((warp_n + (lane & 7) + ((lane >> 4) & 1) * 8) * RROW +
                                     ((lane >> 3) & 1) * 8) * 2;

    for (int c = 0; c < 32; c++) {
        const int jc = j0 + c * 64;
        __syncthreads();
        for (int u = tid; u < 1024; u += 256) {     // red_w tile [64 o][64 j]
            int row = u >> 4, c4 = u & 15;
            float4 wv = *(const float4*)(red_w + (size_t)(o0 + row) * KD + jc + c4 * 4);
            __nv_bfloat16 h0, l0, h1, l1, h2, l2, h3, l3;
            split_bf(wv.x, h0, l0); split_bf(wv.y, h1, l1);
            split_bf(wv.z, h2, l2); split_bf(wv.w, h3, l3);
            *(uint2*)(WH + row * RROW + c4 * 4) = make_uint2(pkbf(h0, h1), pkbf(h2, h3));
            *(uint2*)(WL + row * RROW + c4 * 4) = make_uint2(pkbf(l0, l1), pkbf(l2, l3));
        }
        for (int u = tid; u < 512; u += 256) {      // vlad tile [32 b][64 j], scaled
            int row = u >> 4, c4 = u & 15;
            float bs = sBS[row];
            float4 vv = *(const float4*)(g_vlad + (size_t)row * KD + jc + c4 * 4);
            vv.x *= bs; vv.y *= bs; vv.z *= bs; vv.w *= bs;
            __nv_bfloat16 h0, l0, h1, l1, h2, l2, h3, l3;
            split_bf(vv.x, h0, l0); split_bf(vv.y, h1, l1);
            split_bf(vv.z, h2, l2); split_bf(vv.w, h3, l3);
            *(uint2*)(VH + row * RROW + c4 * 4) = make_uint2(pkbf(h0, h1), pkbf(h2, h3));
            *(uint2*)(VL + row * RROW + c4 * 4) = make_uint2(pkbf(l0, l1), pkbf(l2, l3));
        }
        __syncthreads();

#pragma unroll
        for (int ks = 0; ks < 4; ks++) {
            const uint32_t co = (uint32_t)(ks * 16) * 2;
            uint32_t ah[4], al[4], bh[4], bl[4];
            ldmx4(ah, whb + co + aoff);
            ldmx4(al, wlb + co + aoff);
            ldmx4(bh, vhb + co + boff);
            ldmx4(bl, vlb + co + boff);
            mma_bf16(cacc[0], ah, bh);     mma_bf16(cacc[0], ah, bl);
            mma_bf16(cacc[0], al, bh);
            mma_bf16(cacc[1], ah, bh + 2); mma_bf16(cacc[1], ah, bl + 2);
            mma_bf16(cacc[1], al, bh + 2);
        }
    }

    // writeback: o = o0+warp_m+g (+8); b = warp_n + nt*8 + 2t (+1)
#pragma unroll
    for (int nt = 0; nt < 2; nt++) {
        const int bcol = warp_n + nt * 8 + 2 * t;
        const int oa = o0 + warp_m + g;
        atomicAdd(&g_outpre[(size_t)bcol * OUTN + oa],           cacc[nt][0]);
        atomicAdd(&g_outpre[(size_t)(bcol + 1) * OUTN + oa],     cacc[nt][1]);
        atomicAdd(&g_outpre[(size_t)bcol * OUTN + oa + 8],       cacc[nt][2]);
        atomicAdd(&g_outpre[(size_t)(bcol + 1) * OUTN + oa + 8], cacc[nt][3]);
    }
}

// ================= K5: LayerNorm =================
__global__ __launch_bounds__(256) void k_ln(
    const float* __restrict__ gamma, const float* __restrict__ beta,
    float* __restrict__ out)
{
    __shared__ float sred[8];
    const int b = blockIdx.x, tid = threadIdx.x, lane = tid & 31, w = tid >> 5;
    float4 v = ((const float4*)(g_outpre + (size_t)b * OUTN))[tid];
    float s = v.x + v.y + v.z + v.w;
    s += __shfl_xor_sync(0xffffffffu, s, 16);
    s += __shfl_xor_sync(0xffffffffu, s, 8);
    s += __shfl_xor_sync(0xffffffffu, s, 4);
    s += __shfl_xor_sync(0xffffffffu, s, 2);
    s += __shfl_xor_sync(0xffffffffu, s, 1);
    if (lane == 0) sred[w] = s;
    __syncthreads();
    float tot = 0.f;
#pragma unroll
    for (int i = 0; i < 8; i++) tot += sred[i];
    const float mu = tot * (1.f / 1024.f);
    float dx0 = v.x - mu, dx1 = v.y - mu, dx2 = v.z - mu, dx3 = v.w - mu;
    float vs = dx0 * dx0 + dx1 * dx1 + dx2 * dx2 + dx3 * dx3;
    vs += __shfl_xor_sync(0xffffffffu, vs, 16);
    vs += __shfl_xor_sync(0xffffffffu, vs, 8);
    vs += __shfl_xor_sync(0xffffffffu, vs, 4);
    vs += __shfl_xor_sync(0xffffffffu, vs, 2);
    vs += __shfl_xor_sync(0xffffffffu, vs, 1);
    __syncthreads();
    if (lane == 0) sred[w] = vs;
    __syncthreads();
    float vtot = 0.f;
#pragma unroll
    for (int i = 0; i < 8; i++) vtot += sred[i];
    const float inv = 1.f / sqrtf(vtot * (1.f / 1024.f) + 1e-5f);
    float4 gm = ((const float4*)gamma)[tid];
    float4 be = ((const float4*)beta)[tid];
    float4 r;
    r.x = dx0 * inv * gm.x + be.x;
    r.y = dx1 * inv * gm.y + be.y;
    r.z = dx2 * inv * gm.z + be.z;
    r.w = dx3 * inv * gm.w + be.w;
    ((float4*)(out + (size_t)b * OUTN))[tid] = r;
}

// ================= launch =================
extern "C" void kernel_launch(void* const* d_in, const int* in_sizes, int n_in,
                              void* d_out, int out_size)
{
    const float* x         = (const float*)d_in[0];
    const int*   mask      = (const int*)d_in[1];
    const float* centroids = (const float*)d_in[2];
    const float* conv_w    = (const float*)d_in[3];
    const float* red_w     = (const float*)d_in[4];
    const float* gamma     = (const float*)d_in[5];
    const float* beta      = (const float*)d_in[6];
    float* out = (float*)d_out;

    cudaFuncSetAttribute(k_g1, cudaFuncAttributeMaxDynamicSharedMemorySize, G1_SMEM);
    cudaFuncSetAttribute(k_g2, cudaFuncAttributeMaxDynamicSharedMemorySize, G2_SMEM);

    k_zero<<<BB * KD / 256, 256>>>();
    k_g1<<<dim3(BB, 25), 256, G1_SMEM>>>(x, mask, conv_w);
    k_g2<<<dim3(BB, 4, 4), 256, G2_SMEM>>>(x);
    k_intranorm<<<BB * KK, 128>>>(centroids);
    k_reduce<<<dim3(16, 16), 256>>>(red_w);
    k_ln<<<BB, 256>>>(gamma, beta, out);
}

// round 9
// speedup vs baseline: 4.8787x; 1.6239x over previous
#include <cuda_runtime.h>
#include <cuda_bf16.h>
#include <math.h>
#include <cstdint>

#define BB 32
#define DD 512
#define TT 64
#define RR 49
#define TR 3136
#define KK 64
#define OUTN 1024
#define KD 32768

// ================= mma / ldmatrix =================
__device__ __forceinline__ void mma_bf16(float* c, const uint32_t* a, const uint32_t* b) {
    asm volatile(
        "mma.sync.aligned.m16n8k16.row.col.f32.bf16.bf16.f32 "
        "{%0,%1,%2,%3}, {%4,%5,%6,%7}, {%8,%9}, {%0,%1,%2,%3};"
        : "+f"(c[0]), "+f"(c[1]), "+f"(c[2]), "+f"(c[3])
        : "r"(a[0]), "r"(a[1]), "r"(a[2]), "r"(a[3]), "r"(b[0]), "r"(b[1]));
}
__device__ __forceinline__ void ldmx4(uint32_t* r, uint32_t a) {
    asm volatile("ldmatrix.sync.aligned.m8n8.x4.shared.b16 {%0,%1,%2,%3}, [%4];"
                 : "=r"(r[0]), "=r"(r[1]), "=r"(r[2]), "=r"(r[3]) : "r"(a));
}
__device__ __forceinline__ void ldmx4t(uint32_t* r, uint32_t a) {
    asm volatile("ldmatrix.sync.aligned.m8n8.x4.trans.shared.b16 {%0,%1,%2,%3}, [%4];"
                 : "=r"(r[0]), "=r"(r[1]), "=r"(r[2]), "=r"(r[3]) : "r"(a));
}
__device__ __forceinline__ void ldmx2(uint32_t* r, uint32_t a) {
    asm volatile("ldmatrix.sync.aligned.m8n8.x2.shared.b16 {%0,%1}, [%2];"
                 : "=r"(r[0]), "=r"(r[1]) : "r"(a));
}
__device__ __forceinline__ uint32_t smem_u32(const void* p) {
    uint32_t a;
    asm("{ .reg .u64 t; cvta.to.shared.u64 t, %1; cvt.u32.u64 %0, t; }" : "=r"(a) : "l"(p));
    return a;
}
__device__ __forceinline__ void split_bf(float f, __nv_bfloat16& h, __nv_bfloat16& l) {
    h = __float2bfloat16(f);
    l = __float2bfloat16(f - __bfloat162float(h));
}
__device__ __forceinline__ uint32_t pkbf(__nv_bfloat16 a, __nv_bfloat16 b) {
    return (uint32_t)__bfloat16_as_ushort(a) | ((uint32_t)__bfloat16_as_ushort(b) << 16);
}
__device__ __forceinline__ void split4(float4 v, uint2& vh, uint2& vl) {
    __nv_bfloat16 h0, l0, h1, l1, h2, l2, h3, l3;
    split_bf(v.x, h0, l0); split_bf(v.y, h1, l1);
    split_bf(v.z, h2, l2); split_bf(v.w, h3, l3);
    vh = make_uint2(pkbf(h0, h1), pkbf(h2, h3));
    vl = make_uint2(pkbf(l0, l1), pkbf(l2, l3));
}

// ================= scratch =================
__device__ __align__(256) __nv_bfloat16 g_ass_hi[(size_t)BB * KK * TR];   // 12.8 MB
__device__ __align__(256) __nv_bfloat16 g_ass_lo[(size_t)BB * KK * TR];
__device__ __align__(256) float g_asum[BB * KK];
__device__ __align__(256) float g_vlad[BB * KD];          // 4 MB (accumulated)
__device__ __align__(256) float g_bsq[BB];
__device__ __align__(256) float g_outpre[BB * OUTN];

__global__ void k_zero() {
    int i = blockIdx.x * 256 + threadIdx.x;
    g_vlad[i] = 0.f;
    if (i < BB * OUTN) g_outpre[i] = 0.f;
    if (i < BB * KK)   g_asum[i]   = 0.f;
    if (i < BB)        g_bsq[i]    = 0.f;
}

extern __shared__ unsigned char smx[];

// ================= GEMM1: logits -> softmax -> assign + a_sum =================
// grid (32, 25), block 256 (8 warps). C tile [128 tr x 64 k]; K loop: d chunks of 64.
// x prefetched into registers one chunk ahead (LDG overlaps previous chunk's MMA).
#define X1ROW 136
#define W1ROW 72
#define G1_XH 0
#define G1_XL (64 * X1ROW)
#define G1_WH (2 * 64 * X1ROW)
#define G1_WL (2 * 64 * X1ROW + 64 * W1ROW)
#define G1_END (2 * 64 * X1ROW + 2 * 64 * W1ROW)
#define G1_SMEM (G1_END * 2 + 256)

__global__ __launch_bounds__(256) void k_g1(const float* __restrict__ x,
                                            const int* __restrict__ mask,
                                            const float* __restrict__ conv_w) {
    uint16_t* S = (uint16_t*)smx;
    float* sAs = (float*)(S + G1_END);
    const uint32_t sb = smem_u32(S);
    const int tid = threadIdx.x, wid = tid >> 5, lane = tid & 31;
    const int g = lane >> 2, t = lane & 3;
    const int b = blockIdx.x, tr0 = blockIdx.y * 128;

    if (tid < 64) sAs[tid] = 0.f;

    float cacc[8][4];
#pragma unroll
    for (int n = 0; n < 8; n++)
#pragma unroll
        for (int i = 0; i < 4; i++) cacc[n][i] = 0.f;

    const uint32_t aoff = (uint32_t)(((lane >> 4) * 8 + (lane & 7)) * X1ROW +
                                     wid * 16 + ((lane >> 3) & 1) * 8) * 2;
    const int L = lane & 15;
    const uint32_t boff = (uint32_t)((L & 7) * W1ROW + (L >> 3) * 8) * 2;

    // per-thread staging coords (fixed): u = tid + j*256
    const int xrow[8] = { tid >> 5, (tid + 256) >> 5, (tid + 512) >> 5, (tid + 768) >> 5,
                          (tid + 1024) >> 5, (tid + 1280) >> 5, (tid + 1536) >> 5, (tid + 1792) >> 5 };
    const int xc4 = tid & 31;
    const int xtr = tr0 + xc4 * 4;
    const bool xok = (xtr < TR);

    float4 rx[8];
#pragma unroll
    for (int j = 0; j < 8; j++)
        rx[j] = xok ? *(const float4*)(x + ((size_t)b * DD + xrow[j]) * TR + xtr)
                    : make_float4(0.f, 0.f, 0.f, 0.f);

    for (int q = 0; q < 8; q++) {
        __syncthreads();
#pragma unroll
        for (int j = 0; j < 8; j++) {
            uint2 vh, vl; split4(rx[j], vh, vl);
            *(uint2*)(S + G1_XH + xrow[j] * X1ROW + xc4 * 4) = vh;
            *(uint2*)(S + G1_XL + xrow[j] * X1ROW + xc4 * 4) = vl;
        }
        for (int u = tid; u < 1024; u += 256) {          // W chunk (L2-hot)
            int row = u >> 4, c4 = u & 15;
            float4 wv = *(const float4*)(conv_w + row * DD + q * 64 + c4 * 4);
            uint2 vh, vl; split4(wv, vh, vl);
            *(uint2*)(S + G1_WH + row * W1ROW + c4 * 4) = vh;
            *(uint2*)(S + G1_WL + row * W1ROW + c4 * 4) = vl;
        }
        __syncthreads();

        if (q < 7) {                                     // prefetch next chunk
#pragma unroll
            for (int j = 0; j < 8; j++)
                rx[j] = xok ? *(const float4*)(x + ((size_t)b * DD + (q + 1) * 64 + xrow[j]) * TR + xtr)
                            : make_float4(0.f, 0.f, 0.f, 0.f);
        }

#pragma unroll
        for (int s = 0; s < 4; s++) {
            uint32_t ah[4], al[4];
            ldmx4t(ah, sb + G1_XH * 2 + (uint32_t)(s * 16 * X1ROW) * 2 + aoff);
            ldmx4t(al, sb + G1_XL * 2 + (uint32_t)(s * 16 * X1ROW) * 2 + aoff);
#pragma unroll
            for (int n = 0; n < 8; n++) {
                uint32_t bh[2], bl[2];
                uint32_t bb = (uint32_t)(n * 8 * W1ROW + s * 16) * 2 + boff;
                ldmx2(bh, sb + G1_WH * 2 + bb);
                ldmx2(bl, sb + G1_WL * 2 + bb);
                mma_bf16(cacc[n], ah, bh);
                mma_bf16(cacc[n], ah, bl);
                mma_bf16(cacc[n], al, bh);
            }
        }
    }

    const int tra = tr0 + wid * 16 + g;
    const int trb = tra + 8;
    float ma = -1e30f, mb = -1e30f;
#pragma unroll
    for (int n = 0; n < 8; n++) {
        ma = fmaxf(ma, fmaxf(cacc[n][0], cacc[n][1]));
        mb = fmaxf(mb, fmaxf(cacc[n][2], cacc[n][3]));
    }
    ma = fmaxf(ma, __shfl_xor_sync(0xffffffffu, ma, 1));
    ma = fmaxf(ma, __shfl_xor_sync(0xffffffffu, ma, 2));
    mb = fmaxf(mb, __shfl_xor_sync(0xffffffffu, mb, 1));
    mb = fmaxf(mb, __shfl_xor_sync(0xffffffffu, mb, 2));
    float sa = 0.f, sb2 = 0.f;
#pragma unroll
    for (int n = 0; n < 8; n++) {
        cacc[n][0] = __expf(cacc[n][0] - ma); sa += cacc[n][0];
        cacc[n][1] = __expf(cacc[n][1] - ma); sa += cacc[n][1];
        cacc[n][2] = __expf(cacc[n][2] - mb); sb2 += cacc[n][2];
        cacc[n][3] = __expf(cacc[n][3] - mb); sb2 += cacc[n][3];
    }
    sa  += __shfl_xor_sync(0xffffffffu, sa, 1);
    sa  += __shfl_xor_sync(0xffffffffu, sa, 2);
    sb2 += __shfl_xor_sync(0xffffffffu, sb2, 1);
    sb2 += __shfl_xor_sync(0xffffffffu, sb2, 2);
    const float mva = (tra < TR) ? (float)mask[b * TT + tra / RR] : 0.f;
    const float mvb = (trb < TR) ? (float)mask[b * TT + trb / RR] : 0.f;
    const float inva = mva / sa, invb = mvb / sb2;

#pragma unroll
    for (int n = 0; n < 8; n++) {
#pragma unroll
        for (int i = 0; i < 2; i++) {
            const int k = n * 8 + 2 * t + i;
            float aa = cacc[n][i] * inva;
            float ab = cacc[n][2 + i] * invb;
            if (tra < TR) {
                __nv_bfloat16 h, l; split_bf(aa, h, l);
                size_t o = ((size_t)b * KK + k) * TR + tra;
                g_ass_hi[o] = h; g_ass_lo[o] = l;
            }
            if (trb < TR) {
                __nv_bfloat16 h, l; split_bf(ab, h, l);
                size_t o = ((size_t)b * KK + k) * TR + trb;
                g_ass_hi[o] = h; g_ass_lo[o] = l;
            }
            float sum = aa + ab;
            sum += __shfl_xor_sync(0xffffffffu, sum, 4);
            sum += __shfl_xor_sync(0xffffffffu, sum, 8);
            sum += __shfl_xor_sync(0xffffffffu, sum, 16);
            if (g == 0) atomicAdd(&sAs[k], sum);
        }
    }
    __syncthreads();
    if (tid < 64) atomicAdd(&g_asum[b * 64 + tid], sAs[tid]);
}

// ================= GEMM2: vlad_partial[b,k,d] += sum_tr a*x =================
// grid (32, 4, 4), block 256. x + assign prefetched one chunk ahead.
#define X2ROW 72
#define G2_XH 0
#define G2_XL (128 * X2ROW)
#define G2_AH (2 * 128 * X2ROW)
#define G2_AL (2 * 128 * X2ROW + 64 * X2ROW)
#define G2_END (2 * 128 * X2ROW + 2 * 64 * X2ROW)
#define G2_SMEM (G2_END * 2 + 256)

__global__ __launch_bounds__(256) void k_g2(const float* __restrict__ x) {
    uint16_t* S = (uint16_t*)smx;
    const uint32_t sbb = smem_u32(S);
    const int tid = threadIdx.x, wid = tid >> 5, lane = tid & 31;
    const int g = lane >> 2, t = lane & 3;
    const int b = blockIdx.x, d0 = blockIdx.y * 128, sp = blockIdx.z;
    const int c0 = sp ? 12 * sp + 1 : 0;
    const int c1 = (sp == 3) ? 49 : 12 * (sp + 1) + 1;

    float cacc[8][4];
#pragma unroll
    for (int n = 0; n < 8; n++)
#pragma unroll
        for (int i = 0; i < 4; i++) cacc[n][i] = 0.f;

    const uint32_t aoff = (uint32_t)((wid * 16 + (lane & 15)) * X2ROW + (lane >> 4) * 8) * 2;
    const int L = lane & 15;
    const uint32_t boff = (uint32_t)((L & 7) * X2ROW + (L >> 3) * 8) * 2;

    // staging coords: x u = tid + j*256 (j<8): row=u>>4, c4=u&15 ; assign u = tid + j*256 (j<2)
    const int xrow_lo = tid >> 4, xc4 = tid & 15;
    const int arow_lo = tid >> 3, ac8 = tid & 7;

    float4 rx[8];
    uint4 rah[2], ral[2];
#pragma unroll
    for (int j = 0; j < 8; j++)
        rx[j] = *(const float4*)(x + ((size_t)b * DD + d0 + xrow_lo + j * 16) * TR + c0 * 64 + xc4 * 4);
#pragma unroll
    for (int j = 0; j < 2; j++) {
        size_t src = ((size_t)b * KK + arow_lo + j * 32) * TR + c0 * 64 + ac8 * 8;
        rah[j] = *(const uint4*)(g_ass_hi + src);
        ral[j] = *(const uint4*)(g_ass_lo + src);
    }

    for (int c = c0; c < c1; c++) {
        __syncthreads();
#pragma unroll
        for (int j = 0; j < 8; j++) {
            uint2 vh, vl; split4(rx[j], vh, vl);
            *(uint2*)(S + G2_XH + (xrow_lo + j * 16) * X2ROW + xc4 * 4) = vh;
            *(uint2*)(S + G2_XL + (xrow_lo + j * 16) * X2ROW + xc4 * 4) = vl;
        }
#pragma unroll
        for (int j = 0; j < 2; j++) {
            int row = arow_lo + j * 32;
            *(uint2*)(S + G2_AH + row * X2ROW + ac8 * 8)     = make_uint2(rah[j].x, rah[j].y);
            *(uint2*)(S + G2_AH + row * X2ROW + ac8 * 8 + 4) = make_uint2(rah[j].z, rah[j].w);
            *(uint2*)(S + G2_AL + row * X2ROW + ac8 * 8)     = make_uint2(ral[j].x, ral[j].y);
            *(uint2*)(S + G2_AL + row * X2ROW + ac8 * 8 + 4) = make_uint2(ral[j].z, ral[j].w);
        }
        __syncthreads();

        if (c + 1 < c1) {
            const int trn = (c + 1) * 64;
#pragma unroll
            for (int j = 0; j < 8; j++)
                rx[j] = *(const float4*)(x + ((size_t)b * DD + d0 + xrow_lo + j * 16) * TR + trn + xc4 * 4);
#pragma unroll
            for (int j = 0; j < 2; j++) {
                size_t src = ((size_t)b * KK + arow_lo + j * 32) * TR + trn + ac8 * 8;
                rah[j] = *(const uint4*)(g_ass_hi + src);
                ral[j] = *(const uint4*)(g_ass_lo + src);
            }
        }

#pragma unroll
        for (int s = 0; s < 4; s++) {
            uint32_t ah[4], al[4];
            ldmx4(ah, sbb + G2_XH * 2 + (uint32_t)(s * 16) * 2 + aoff);
            ldmx4(al, sbb + G2_XL * 2 + (uint32_t)(s * 16) * 2 + aoff);
#pragma unroll
            for (int n = 0; n < 8; n++) {
                uint32_t bh[2], bl[2];
                uint32_t bb = (uint32_t)(n * 8 * X2ROW + s * 16) * 2 + boff;
                ldmx2(bh, sbb + G2_AH * 2 + bb);
                ldmx2(bl, sbb + G2_AL * 2 + bb);
                mma_bf16(cacc[n], ah, bh);
                mma_bf16(cacc[n], ah, bl);
                mma_bf16(cacc[n], al, bh);
            }
        }
    }

    const int da = d0 + wid * 16 + g;
    const int db = da + 8;
#pragma unroll
    for (int n = 0; n < 8; n++) {
#pragma unroll
        for (int i = 0; i < 2; i++) {
            const int k = n * 8 + 2 * t + i;
            atomicAdd(&g_vlad[((size_t)b * KK + k) * DD + da], cacc[n][i]);
            atomicAdd(&g_vlad[((size_t)b * KK + k) * DD + db], cacc[n][2 + i]);
        }
    }
}

// ================= K3: subtract a_sum*centroid, intra-norm, per-b sumsq =================
__global__ __launch_bounds__(128) void k_intranorm(const float* __restrict__ centroids) {
    __shared__ float sred[4];
    const int row = blockIdx.x;
    const int tid = threadIdx.x, lane = tid & 31, w = tid >> 5;
    const float as = g_asum[row];
    float4* v = (float4*)(g_vlad + (size_t)row * 512);
    float4 val = v[tid];
    const float4 cv = ((const float4*)(centroids + (size_t)(row & 63) * DD))[tid];
    val.x -= as * cv.x; val.y -= as * cv.y; val.z -= as * cv.z; val.w -= as * cv.w;
    float ss = val.x * val.x + val.y * val.y + val.z * val.z + val.w * val.w;
    ss += __shfl_xor_sync(0xffffffffu, ss, 16);
    ss += __shfl_xor_sync(0xffffffffu, ss, 8);
    ss += __shfl_xor_sync(0xffffffffu, ss, 4);
    ss += __shfl_xor_sync(0xffffffffu, ss, 2);
    ss += __shfl_xor_sync(0xffffffffu, ss, 1);
    if (lane == 0) sred[w] = ss;
    __syncthreads();
    float tot = sred[0] + sred[1] + sred[2] + sred[3];
    float scale = 1.f / fmaxf(sqrtf(tot), 1e-12f);
    val.x *= scale; val.y *= scale; val.z *= scale; val.w *= scale;
    v[tid] = val;
    if (tid == 0) atomicAdd(&g_bsq[row >> 6], tot * scale * scale);
}

// ================= K4: reduction GEMM on HMMA (prefetched staging) =================
#define RROW 72
__global__ __launch_bounds__(256) void k_reduce(const float* __restrict__ red_w) {
    __shared__ uint16_t WH[64 * RROW], WL[64 * RROW];
    __shared__ uint16_t VH[32 * RROW], VL[32 * RROW];
    __shared__ float sBS[32];
    const int tid = threadIdx.x, wid = tid >> 5, lane = tid & 31;
    const int g = lane >> 2, t = lane & 3;
    const int o0 = blockIdx.x * 64;
    const int j0 = blockIdx.y * 2048;
    const int warp_m = (wid & 3) * 16;
    const int warp_n = (wid >> 2) * 16;

    if (tid < 32) sBS[tid] = 1.f / fmaxf(sqrtf(g_bsq[tid]), 1e-12f);
    __syncthreads();

    float cacc[2][4];
#pragma unroll
    for (int n = 0; n < 2; n++)
#pragma unroll
        for (int i = 0; i < 4; i++) cacc[n][i] = 0.f;

    const uint32_t whb = smem_u32(WH), wlb = smem_u32(WL);
    const uint32_t vhb = smem_u32(VH), vlb = smem_u32(VL);
    const uint32_t aoff = (uint32_t)((warp_m + (lane & 15)) * RROW + (lane >> 4) * 8) * 2;
    const uint32_t boff = (uint32_t)((warp_n + (lane & 7) + ((lane >> 4) & 1) * 8) * RROW +
                                     ((lane >> 3) & 1) * 8) * 2;

    // staging coords: W u = tid + j*256 (j<4): row=u>>4,c4=u&15 ; V u = tid + j*256 (j<2): row=u>>4
    const int wrow_lo = tid >> 4, wc4 = tid & 15;

    float4 rw[4], rv[2];
#pragma unroll
    for (int j = 0; j < 4; j++)
        rw[j] = *(const float4*)(red_w + (size_t)(o0 + wrow_lo + j * 16) * KD + j0 + wc4 * 4);
#pragma unroll
    for (int j = 0; j < 2; j++)
        rv[j] = *(const float4*)(g_vlad + (size_t)(wrow_lo + j * 16) * KD + j0 + wc4 * 4);

    for (int c = 0; c < 32; c++) {
        __syncthreads();
#pragma unroll
        for (int j = 0; j < 4; j++) {
            uint2 vh, vl; split4(rw[j], vh, vl);
            *(uint2*)(WH + (wrow_lo + j * 16) * RROW + wc4 * 4) = vh;
            *(uint2*)(WL + (wrow_lo + j * 16) * RROW + wc4 * 4) = vl;
        }
#pragma unroll
        for (int j = 0; j < 2; j++) {
            int row = wrow_lo + j * 16;
            float bs = sBS[row];
            float4 vv = rv[j];
            vv.x *= bs; vv.y *= bs; vv.z *= bs; vv.w *= bs;
            uint2 vh, vl; split4(vv, vh, vl);
            *(uint2*)(VH + row * RROW + wc4 * 4) = vh;
            *(uint2*)(VL + row * RROW + wc4 * 4) = vl;
        }
        __syncthreads();

        if (c + 1 < 32) {
            const int jc = j0 + (c + 1) * 64;
#pragma unroll
            for (int j = 0; j < 4; j++)
                rw[j] = *(const float4*)(red_w + (size_t)(o0 + wrow_lo + j * 16) * KD + jc + wc4 * 4);
#pragma unroll
            for (int j = 0; j < 2; j++)
                rv[j] = *(const float4*)(g_vlad + (size_t)(wrow_lo + j * 16) * KD + jc + wc4 * 4);
        }

#pragma unroll
        for (int ks = 0; ks < 4; ks++) {
            const uint32_t co = (uint32_t)(ks * 16) * 2;
            uint32_t ah[4], al[4], bh[4], bl[4];
            ldmx4(ah, whb + co + aoff);
            ldmx4(al, wlb + co + aoff);
            ldmx4(bh, vhb + co + boff);
            ldmx4(bl, vlb + co + boff);
            mma_bf16(cacc[0], ah, bh);     mma_bf16(cacc[0], ah, bl);
            mma_bf16(cacc[0], al, bh);
            mma_bf16(cacc[1], ah, bh + 2); mma_bf16(cacc[1], ah, bl + 2);
            mma_bf16(cacc[1], al, bh + 2);
        }
    }

#pragma unroll
    for (int nt = 0; nt < 2; nt++) {
        const int bcol = warp_n + nt * 8 + 2 * t;
        const int oa = o0 + warp_m + g;
        atomicAdd(&g_outpre[(size_t)bcol * OUTN + oa],           cacc[nt][0]);
        atomicAdd(&g_outpre[(size_t)(bcol + 1) * OUTN + oa],     cacc[nt][1]);
        atomicAdd(&g_outpre[(size_t)bcol * OUTN + oa + 8],       cacc[nt][2]);
        atomicAdd(&g_outpre[(size_t)(bcol + 1) * OUTN + oa + 8], cacc[nt][3]);
    }
}

// ================= K5: LayerNorm =================
__global__ __launch_bounds__(256) void k_ln(
    const float* __restrict__ gamma, const float* __restrict__ beta,
    float* __restrict__ out)
{
    __shared__ float sred[8];
    const int b = blockIdx.x, tid = threadIdx.x, lane = tid & 31, w = tid >> 5;
    float4 v = ((const float4*)(g_outpre + (size_t)b * OUTN))[tid];
    float s = v.x + v.y + v.z + v.w;
    s += __shfl_xor_sync(0xffffffffu, s, 16);
    s += __shfl_xor_sync(0xffffffffu, s, 8);
    s += __shfl_xor_sync(0xffffffffu, s, 4);
    s += __shfl_xor_sync(0xffffffffu, s, 2);
    s += __shfl_xor_sync(0xffffffffu, s, 1);
    if (lane == 0) sred[w] = s;
    __syncthreads();
    float tot = 0.f;
#pragma unroll
    for (int i = 0; i < 8; i++) tot += sred[i];
    const float mu = tot * (1.f / 1024.f);
    float dx0 = v.x - mu, dx1 = v.y - mu, dx2 = v.z - mu, dx3 = v.w - mu;
    float vs = dx0 * dx0 + dx1 * dx1 + dx2 * dx2 + dx3 * dx3;
    vs += __shfl_xor_sync(0xffffffffu, vs, 16);
    vs += __shfl_xor_sync(0xffffffffu, vs, 8);
    vs += __shfl_xor_sync(0xffffffffu, vs, 4);
    vs += __shfl_xor_sync(0xffffffffu, vs, 2);
    vs += __shfl_xor_sync(0xffffffffu, vs, 1);
    __syncthreads();
    if (lane == 0) sred[w] = vs;
    __syncthreads();
    float vtot = 0.f;
#pragma unroll
    for (int i = 0; i < 8; i++) vtot += sred[i];
    const float inv = 1.f / sqrtf(vtot * (1.f / 1024.f) + 1e-5f);
    float4 gm = ((const float4*)gamma)[tid];
    float4 be = ((const float4*)beta)[tid];
    float4 r;
    r.x = dx0 * inv * gm.x + be.x;
    r.y = dx1 * inv * gm.y + be.y;
    r.z = dx2 * inv * gm.z + be.z;
    r.w = dx3 * inv * gm.w + be.w;
    ((float4*)(out + (size_t)b * OUTN))[tid] = r;
}

// ================= launch =================
extern "C" void kernel_launch(void* const* d_in, const int* in_sizes, int n_in,
                              void* d_out, int out_size)
{
    const float* x         = (const float*)d_in[0];
    const int*   mask      = (const int*)d_in[1];
    const float* centroids = (const float*)d_in[2];
    const float* conv_w    = (const float*)d_in[3];
    const float* red_w     = (const float*)d_in[4];
    const float* gamma     = (const float*)d_in[5];
    const float* beta      = (const float*)d_in[6];
    float* out = (float*)d_out;

    cudaFuncSetAttribute(k_g1, cudaFuncAttributeMaxDynamicSharedMemorySize, G1_SMEM);
    cudaFuncSetAttribute(k_g2, cudaFuncAttributeMaxDynamicSharedMemorySize, G2_SMEM);

    k_zero<<<BB * KD / 256, 256>>>();
    k_g1<<<dim3(BB, 25), 256, G1_SMEM>>>(x, mask, conv_w);
    k_g2<<<dim3(BB, 4, 4), 256, G2_SMEM>>>(x);
    k_intranorm<<<BB * KK, 128>>>(centroids);
    k_reduce<<<dim3(16, 16), 256>>>(red_w);
    k_ln<<<BB, 256>>>(gamma, beta, out);
}